// round 1
// baseline (speedup 1.0000x reference)
#include <cuda_runtime.h>

#define NN 8
#define CC 128
#define LL 512
#define DD 64
#define FF 512
#define LN_EPS 1e-5f
#define ATTN_EPS 1e-6f

// ---------------- scratch (static device globals; no allocation) ----------------
__device__ float g_xt[NN*LL*CC];   // (n,l,c)  2MB
__device__ float g_q [NN*LL*DD];   // q + bh   1MB
__device__ float g_k [NN*LL*DD];   // k        1MB
__device__ float g_x2[NN*LL*CC];   // post-LN0 2MB
__device__ float g_H [NN*LL*FF];   // hidden   8MB

__device__ __forceinline__ float tanh_fast(float x) {
    // (1-e)/(1+e) with e = exp(-2|x|); ~1e-6 rel accuracy, 2 MUFU
    float e = __expf(-2.0f * fabsf(x));
    float t = __fdividef(1.0f - e, 1.0f + e);
    return copysignf(t, x);
}

// ---------------- K1: transpose x -> xt, compute q'=xt@Wt+bh, k=xt@Wx ----------------
__global__ __launch_bounds__(256) void k_prep(
    const float* __restrict__ x, const float* __restrict__ Wt,
    const float* __restrict__ Wx, const float* __restrict__ bh) {
    __shared__ float xs[CC][65];
    int n = blockIdx.y, l0 = blockIdx.x * 64;
    const float* xp = x + n*CC*LL + l0;
    for (int idx = threadIdx.x; idx < CC*64; idx += 256) {
        int c = idx >> 6, l = idx & 63;
        xs[c][l] = xp[c*LL + l];
    }
    __syncthreads();
    float* xtp = g_xt + (n*LL + l0)*CC;
    for (int idx = threadIdx.x; idx < 64*CC; idx += 256) {
        int l = idx >> 7, c = idx & 127;
        xtp[l*CC + c] = xs[c][l];
    }
    int l  = threadIdx.x >> 2;
    int d0 = (threadIdx.x & 3) * 16;
    float aq[16], ak[16];
    #pragma unroll
    for (int j = 0; j < 16; j++) { aq[j] = bh[d0+j]; ak[j] = 0.f; }
    for (int c = 0; c < CC; c++) {
        float xv = xs[c][l];
        const float4* wt4 = (const float4*)(Wt + c*DD + d0);
        const float4* wx4 = (const float4*)(Wx + c*DD + d0);
        #pragma unroll
        for (int j4 = 0; j4 < 4; j4++) {
            float4 wt = __ldg(wt4 + j4);
            float4 wx = __ldg(wx4 + j4);
            aq[j4*4+0] += xv*wt.x; aq[j4*4+1] += xv*wt.y;
            aq[j4*4+2] += xv*wt.z; aq[j4*4+3] += xv*wt.w;
            ak[j4*4+0] += xv*wx.x; ak[j4*4+1] += xv*wx.y;
            ak[j4*4+2] += xv*wx.z; ak[j4*4+3] += xv*wx.w;
        }
    }
    float* qp = g_q + (n*LL + l0 + l)*DD + d0;
    float* kp = g_k + (n*LL + l0 + l)*DD + d0;
    #pragma unroll
    for (int j = 0; j < 16; j++) { qp[j] = aq[j]; kp[j] = ak[j]; }
}

// ---------------- K2: scores -> full-row max -> band exp/normalize -> write a ----------------
// block: 16 l-rows of one n; 256 threads; thread = (l = tid&15, m-group = tid>>4 owning 4 m)
__global__ __launch_bounds__(256) void k_scores(
    const float* __restrict__ Wa, float* __restrict__ aout) {
    __shared__ float  kbuf[80][68];
    __shared__ float4 was4[16];
    __shared__ float  eb[16][64];
    __shared__ float  red[8][16];
    __shared__ float  rowmaxs[16];
    __shared__ float  invs[16];

    int n = blockIdx.y, l0 = blockIdx.x * 16;
    int tid = threadIdx.x;
    int l = tid & 15, mg = tid >> 4;
    int li = l0 + l;
    int wid = tid >> 5, lane = tid & 31;

    if (tid < 16) {
        float4 w;
        w.x = Wa[tid*4+0]; w.y = Wa[tid*4+1]; w.z = Wa[tid*4+2]; w.w = Wa[tid*4+3];
        was4[tid] = w;
    }
    // q row (already includes bh) in registers
    float4 rq[16];
    const float4* qrow = (const float4*)(g_q + (n*LL + li)*DD);
    #pragma unroll
    for (int dq = 0; dq < 16; dq++) rq[dq] = qrow[dq];
    __syncthreads();

    const float* kbase = g_k + n*LL*DD;
    float rmax = -1e30f;

    // ---- Phase A: full-row max over all 512 m ----
    for (int mt = 0; mt < LL; mt += 64) {
        #pragma unroll
        for (int i = 0; i < 4; i++) {
            int idx4 = tid + i*256;
            int r = idx4 >> 4, dq = idx4 & 15;
            float4 v = __ldg((const float4*)(kbase + (mt + r)*DD) + dq);
            *(float4*)&kbuf[r][dq*4] = v;
        }
        __syncthreads();
        float s[4] = {0.f, 0.f, 0.f, 0.f};
        int r0 = mg * 4;
        #pragma unroll 4
        for (int dq = 0; dq < 16; dq++) {
            float4 w = was4[dq];
            float4 q = rq[dq];
            #pragma unroll
            for (int j = 0; j < 4; j++) {
                float4 k4 = *(const float4*)&kbuf[r0+j][dq*4];
                float acc;
                acc  = w.x * tanh_fast(q.x + k4.x);
                acc += w.y * tanh_fast(q.y + k4.y);
                acc += w.z * tanh_fast(q.z + k4.z);
                acc += w.w * tanh_fast(q.w + k4.w);
                s[j] += acc;
            }
        }
        rmax = fmaxf(rmax, fmaxf(fmaxf(s[0], s[1]), fmaxf(s[2], s[3])));
        __syncthreads();
    }
    // reduce max over threads sharing l
    rmax = fmaxf(rmax, __shfl_xor_sync(0xffffffffu, rmax, 16));
    if (lane < 16) red[wid][lane] = rmax;
    __syncthreads();
    if (tid < 16) {
        float m = red[0][tid];
        #pragma unroll
        for (int w = 1; w < 8; w++) m = fmaxf(m, red[w][tid]);
        rowmaxs[tid] = m;
    }
    __syncthreads();

    // ---- Phase B: band [li-32, li+31], exp + normalize ----
    int mlo = l0 - 32; if (mlo < 0) mlo = 0;
    int mhi = l0 + 46; if (mhi > LL-1) mhi = LL-1;
    int nm  = mhi - mlo + 1;  // <= 79
    for (int idx4 = tid; idx4 < nm*16; idx4 += 256) {
        int r = idx4 >> 4, dq = idx4 & 15;
        float4 v = __ldg((const float4*)(kbase + (mlo + r)*DD) + dq);
        *(float4*)&kbuf[r][dq*4] = v;
    }
    __syncthreads();
    float rm = rowmaxs[l];
    float esum = 0.f;
    #pragma unroll
    for (int jj = 0; jj < 4; jj++) {
        int mo = mg*4 + jj;
        int m  = li - 32 + mo;
        float e = 0.f;
        if (m >= 0 && m < LL) {
            int r = m - mlo;
            float s = 0.f;
            #pragma unroll 4
            for (int dq = 0; dq < 16; dq++) {
                float4 w = was4[dq];
                float4 q = rq[dq];
                float4 k4 = *(const float4*)&kbuf[r][dq*4];
                s += w.x * tanh_fast(q.x + k4.x);
                s += w.y * tanh_fast(q.y + k4.y);
                s += w.z * tanh_fast(q.z + k4.z);
                s += w.w * tanh_fast(q.w + k4.w);
            }
            e = __expf(s - rm);
        }
        eb[l][mo] = e;
        esum += e;
    }
    esum += __shfl_xor_sync(0xffffffffu, esum, 16);
    if (lane < 16) red[wid][lane] = esum;
    __syncthreads();
    if (tid < 16) {
        float s = 0.f;
        #pragma unroll
        for (int w = 0; w < 8; w++) s += red[w][tid];
        invs[tid] = __fdividef(1.0f, s + ATTN_EPS);
    }
    __syncthreads();
    // write full a rows (zeros outside band)
    float* ar = aout + (n*LL + l0)*LL;
    for (int idx = tid; idx < 16*LL; idx += 256) {
        int ll = idx >> 9, m = idx & 511;
        int mo = m - (l0 + ll - 32);
        float val = 0.f;
        if (mo >= 0 && mo < 64) val = eb[ll][mo] * invs[ll];
        ar[ll*LL + m] = val;
    }
}

// ---------------- K3: v = a@xt (band), residual, LN0 -> g_x2 ----------------
__global__ __launch_bounds__(128) void k_attnln(
    const float* __restrict__ aout, const float* __restrict__ g0,
    const float* __restrict__ be0) {
    int row = blockIdx.x;  // n*LL + li
    int n = row >> 9, li = row & 511;
    __shared__ float ab[64];
    __shared__ float redA[4], redB[4];
    int tid = threadIdx.x;
    int mlo = li - 32; if (mlo < 0) mlo = 0;
    int mhi = li + 31; if (mhi > LL-1) mhi = LL-1;
    int nm  = mhi - mlo + 1;
    if (tid < nm) ab[tid] = aout[row*LL + mlo + tid];
    __syncthreads();
    const float* xtn = g_xt + n*LL*CC;
    float acc = 0.f;
    #pragma unroll 8
    for (int j = 0; j < nm; j++) acc += ab[j] * xtn[(mlo+j)*CC + tid];
    float r = acc + xtn[li*CC + tid];
    float s1 = r, s2 = r*r;
    #pragma unroll
    for (int o = 16; o > 0; o >>= 1) {
        s1 += __shfl_xor_sync(0xffffffffu, s1, o);
        s2 += __shfl_xor_sync(0xffffffffu, s2, o);
    }
    if ((tid & 31) == 0) { redA[tid>>5] = s1; redB[tid>>5] = s2; }
    __syncthreads();
    float S1 = redA[0]+redA[1]+redA[2]+redA[3];
    float S2 = redB[0]+redB[1]+redB[2]+redB[3];
    float mu  = S1 * (1.0f/CC);
    float var = S2 * (1.0f/CC) - mu*mu;
    float y = (r - mu) * rsqrtf(var + LN_EPS) * g0[tid] + be0[tid];
    g_x2[row*CC + tid] = y;
}

// ---------------- K4: H = relu(x2 @ W0 + b0) ----------------
// tile 128x64, 256 threads, 8x4 micro
__global__ __launch_bounds__(256) void k_ffn1(
    const float* __restrict__ W0, const float* __restrict__ b0) {
    __shared__ float As[16][132];
    __shared__ float Bs[16][68];
    int mb = blockIdx.x * 128;
    int cb = blockIdx.y * 64;
    int tid = threadIdx.x;
    int r0 = (tid >> 4) * 8;
    int c0 = (tid & 15) * 4;
    float acc[8][4];
    #pragma unroll
    for (int i = 0; i < 8; i++)
        #pragma unroll
        for (int j = 0; j < 4; j++) acc[i][j] = 0.f;

    for (int kc = 0; kc < CC; kc += 16) {
        #pragma unroll
        for (int i = 0; i < 2; i++) {
            int idx4 = tid + i*256;
            int m = idx4 >> 2, kq = idx4 & 3;
            float4 v = *(const float4*)(g_x2 + (mb+m)*CC + kc + kq*4);
            As[kq*4+0][m] = v.x; As[kq*4+1][m] = v.y;
            As[kq*4+2][m] = v.z; As[kq*4+3][m] = v.w;
        }
        {
            int k = tid >> 4, cq = tid & 15;
            float4 v = __ldg((const float4*)(W0 + (kc+k)*FF + cb + cq*4));
            *(float4*)&Bs[k][cq*4] = v;
        }
        __syncthreads();
        #pragma unroll
        for (int k = 0; k < 16; k++) {
            float4 a0 = *(const float4*)&As[k][r0];
            float4 a1 = *(const float4*)&As[k][r0+4];
            float4 b  = *(const float4*)&Bs[k][c0];
            float av[8] = {a0.x,a0.y,a0.z,a0.w,a1.x,a1.y,a1.z,a1.w};
            float bv[4] = {b.x,b.y,b.z,b.w};
            #pragma unroll
            for (int i = 0; i < 8; i++)
                #pragma unroll
                for (int j = 0; j < 4; j++) acc[i][j] += av[i]*bv[j];
        }
        __syncthreads();
    }
    float4 bb = *(const float4*)(b0 + cb + c0);
    float bv[4] = {bb.x, bb.y, bb.z, bb.w};
    #pragma unroll
    for (int i = 0; i < 8; i++) {
        float4 o;
        o.x = fmaxf(acc[i][0]+bv[0], 0.f);
        o.y = fmaxf(acc[i][1]+bv[1], 0.f);
        o.z = fmaxf(acc[i][2]+bv[2], 0.f);
        o.w = fmaxf(acc[i][3]+bv[3], 0.f);
        *(float4*)(g_H + (mb+r0+i)*FF + cb + c0) = o;
    }
}

// ---------------- K5: x3 = H @ W1 + b1; x4 = LN1(x3 + x2); write transposed out ----------------
// tile 32x128 (full C), 256 threads, 4x4 micro; warp = 32 lanes over one row-group
__global__ __launch_bounds__(256) void k_ffn2(
    const float* __restrict__ W1, const float* __restrict__ b1,
    const float* __restrict__ g1, const float* __restrict__ be1,
    float* __restrict__ out) {
    __shared__ float As[16][40];
    __shared__ float Bs[16][132];
    int mb = blockIdx.x * 32;
    int tid = threadIdx.x;
    int rg = tid >> 5, cg = tid & 31;
    int r0 = rg * 4, c0 = cg * 4;
    float acc[4][4];
    #pragma unroll
    for (int i = 0; i < 4; i++)
        #pragma unroll
        for (int j = 0; j < 4; j++) acc[i][j] = 0.f;

    for (int kc = 0; kc < FF; kc += 16) {
        if (tid < 128) {
            int m = tid >> 2, kq = tid & 3;
            float4 v = *(const float4*)(g_H + (mb+m)*FF + kc + kq*4);
            As[kq*4+0][m] = v.x; As[kq*4+1][m] = v.y;
            As[kq*4+2][m] = v.z; As[kq*4+3][m] = v.w;
        }
        #pragma unroll
        for (int i = 0; i < 2; i++) {
            int idx4 = tid + i*256;
            int k = idx4 >> 5, cq = idx4 & 31;
            float4 v = __ldg((const float4*)(W1 + (kc+k)*CC + cq*4));
            *(float4*)&Bs[k][cq*4] = v;
        }
        __syncthreads();
        #pragma unroll
        for (int k = 0; k < 16; k++) {
            float4 a = *(const float4*)&As[k][r0];
            float4 b = *(const float4*)&Bs[k][c0];
            float av[4] = {a.x,a.y,a.z,a.w};
            float bv[4] = {b.x,b.y,b.z,b.w};
            #pragma unroll
            for (int i = 0; i < 4; i++)
                #pragma unroll
                for (int j = 0; j < 4; j++) acc[i][j] += av[i]*bv[j];
        }
        __syncthreads();
    }
    float4 b1v = *(const float4*)(b1 + c0);
    float4 g1v = *(const float4*)(g1 + c0);
    float4 e1v = *(const float4*)(be1 + c0);
    float bb[4] = {b1v.x,b1v.y,b1v.z,b1v.w};
    float gg[4] = {g1v.x,g1v.y,g1v.z,g1v.w};
    float ee[4] = {e1v.x,e1v.y,e1v.z,e1v.w};
    #pragma unroll
    for (int i = 0; i < 4; i++) {
        int row = mb + r0 + i;
        float4 x2v = *(const float4*)(g_x2 + row*CC + c0);
        float rv[4];
        rv[0] = acc[i][0] + bb[0] + x2v.x;
        rv[1] = acc[i][1] + bb[1] + x2v.y;
        rv[2] = acc[i][2] + bb[2] + x2v.z;
        rv[3] = acc[i][3] + bb[3] + x2v.w;
        float s1 = rv[0]+rv[1]+rv[2]+rv[3];
        float s2 = rv[0]*rv[0]+rv[1]*rv[1]+rv[2]*rv[2]+rv[3]*rv[3];
        #pragma unroll
        for (int o = 16; o > 0; o >>= 1) {
            s1 += __shfl_xor_sync(0xffffffffu, s1, o);
            s2 += __shfl_xor_sync(0xffffffffu, s2, o);
        }
        float mu  = s1 * (1.0f/CC);
        float var = s2 * (1.0f/CC) - mu*mu;
        float inv = rsqrtf(var + LN_EPS);
        int n = row >> 9, ll = row & 511;
        float* op = out + n*CC*LL + ll;
        #pragma unroll
        for (int j = 0; j < 4; j++) {
            float y = (rv[j] - mu) * inv * gg[j] + ee[j];
            op[(c0+j)*LL] = y;
        }
    }
}

// ---------------- launch ----------------
extern "C" void kernel_launch(void* const* d_in, const int* in_sizes, int n_in,
                              void* d_out, int out_size) {
    const float* x   = (const float*)d_in[0];
    const float* Wx  = (const float*)d_in[1];
    const float* Wt  = (const float*)d_in[2];
    const float* bh  = (const float*)d_in[3];
    const float* Wa  = (const float*)d_in[4];
    // d_in[5] = ba: cancels in softmax (exp(s+ba - max(s+ba)) == exp(s - max s)); unused
    const float* W0  = (const float*)d_in[6];
    const float* b0  = (const float*)d_in[7];
    const float* W1  = (const float*)d_in[8];
    const float* b1  = (const float*)d_in[9];
    const float* g0  = (const float*)d_in[10];
    const float* be0 = (const float*)d_in[11];
    const float* g1  = (const float*)d_in[12];
    const float* be1 = (const float*)d_in[13];
    float* out  = (float*)d_out;
    float* aout = out + NN*CC*LL;  // second output: a (N,L,L)

    k_prep  <<<dim3(LL/64, NN), 256>>>(x, Wt, Wx, bh);
    k_scores<<<dim3(LL/16, NN), 256>>>(Wa, aout);
    k_attnln<<<NN*LL, 128>>>(aout, g0, be0);
    k_ffn1  <<<dim3(NN*LL/128, FF/64), 256>>>(W0, b0);
    k_ffn2  <<<NN*LL/32, 256>>>(W1, b1, g1, be1, out);
}

// round 2
// speedup vs baseline: 1.8257x; 1.8257x over previous
#include <cuda_runtime.h>

#define NN 8
#define CC 128
#define LL 512
#define DD 64
#define FF 512
#define LN_EPS 1e-5f
#define ATTN_EPS 1e-6f
#define PS (NN*LL*CC)

// ---------------- scratch (static device globals; no allocation) ----------------
__device__ float g_xt[NN*LL*CC];   // (n,l,c)  2MB
__device__ float g_q [NN*LL*DD];   // q + bh   1MB
__device__ float g_k [NN*LL*DD];   // k        1MB
__device__ float g_x2[NN*LL*CC];   // post-LN0 2MB
__device__ float g_H [NN*LL*FF];   // hidden   8MB
__device__ float g_p [4*NN*LL*CC]; // ffn2 split-K partials 8MB

__device__ __forceinline__ float tanh_fast(float x) {
    float e = __expf(-2.0f * fabsf(x));
    float t = __fdividef(1.0f - e, 1.0f + e);
    return copysignf(t, x);
}

__device__ __forceinline__ void fma2(unsigned long long& acc, unsigned long long a,
                                     unsigned long long b) {
    asm("fma.rn.f32x2 %0, %1, %2, %0;" : "+l"(acc) : "l"(a), "l"(b));
}
__device__ __forceinline__ unsigned long long dup2(float a) {
    unsigned long long r;
    asm("mov.b64 %0, {%1, %1};" : "=l"(r) : "f"(a));
    return r;
}
__device__ __forceinline__ void unpack2(unsigned long long v, float& lo, float& hi) {
    asm("mov.b64 {%0, %1}, %2;" : "=f"(lo), "=f"(hi) : "l"(v));
}

// ---------------- K1: transpose x -> xt, compute q'=xt@Wt+bh, k=xt@Wx ----------------
__global__ __launch_bounds__(256) void k_prep(
    const float* __restrict__ x, const float* __restrict__ Wt,
    const float* __restrict__ Wx, const float* __restrict__ bh) {
    __shared__ float xs[CC][65];
    int n = blockIdx.y, l0 = blockIdx.x * 64;
    const float* xp = x + n*CC*LL + l0;
    for (int idx = threadIdx.x; idx < CC*64; idx += 256) {
        int c = idx >> 6, l = idx & 63;
        xs[c][l] = xp[c*LL + l];
    }
    __syncthreads();
    float* xtp = g_xt + (n*LL + l0)*CC;
    for (int idx = threadIdx.x; idx < 64*CC; idx += 256) {
        int l = idx >> 7, c = idx & 127;
        xtp[l*CC + c] = xs[c][l];
    }
    int l  = threadIdx.x >> 2;
    int d0 = (threadIdx.x & 3) * 16;
    float aq[16], ak[16];
    #pragma unroll
    for (int j = 0; j < 16; j++) { aq[j] = bh[d0+j]; ak[j] = 0.f; }
    for (int c = 0; c < CC; c++) {
        float xv = xs[c][l];
        const float4* wt4 = (const float4*)(Wt + c*DD + d0);
        const float4* wx4 = (const float4*)(Wx + c*DD + d0);
        #pragma unroll
        for (int j4 = 0; j4 < 4; j4++) {
            float4 wt = __ldg(wt4 + j4);
            float4 wx = __ldg(wx4 + j4);
            aq[j4*4+0] += xv*wt.x; aq[j4*4+1] += xv*wt.y;
            aq[j4*4+2] += xv*wt.z; aq[j4*4+3] += xv*wt.w;
            ak[j4*4+0] += xv*wx.x; ak[j4*4+1] += xv*wx.y;
            ak[j4*4+2] += xv*wx.z; ak[j4*4+3] += xv*wx.w;
        }
    }
    float* qp = g_q + (n*LL + l0 + l)*DD + d0;
    float* kp = g_k + (n*LL + l0 + l)*DD + d0;
    #pragma unroll
    for (int j = 0; j < 16; j++) { qp[j] = aq[j]; kp[j] = ak[j]; }
}

// ---------------- K2: band scores (band-max softmax) + a write + attn-apply + LN0 ----------------
// block: 16 l-rows of one n; 256 threads; thread = (l = tid&15, group = tid>>4)
__global__ __launch_bounds__(256) void k_scores_fused(
    const float* __restrict__ Wa, const float* __restrict__ g0,
    const float* __restrict__ be0, float* __restrict__ aout) {
    __shared__ float  buf[79][132];   // k band rows (cols 0..63), then xt band rows (0..127)
    __shared__ float  eb[16][65];     // unnormalized band e
    __shared__ float4 was4[16];
    __shared__ float  redA[8][16];
    __shared__ float  redB[8][16];
    __shared__ float  rowmax[16], invs[16], muA[16], rsA[16];

    int n = blockIdx.y, l0 = blockIdx.x * 16;
    int tid = threadIdx.x;
    int l = tid & 15, mg = tid >> 4;
    int li = l0 + l;
    int wid = tid >> 5, lane = tid & 31;

    int mlo = l0 - 32; if (mlo < 0) mlo = 0;
    int mhi = l0 + 46; if (mhi > LL-1) mhi = LL-1;
    int nm  = mhi - mlo + 1;   // <= 79

    if (tid < 16) was4[tid] = *(const float4*)(Wa + tid*4);

    float4 rq[16];
    const float4* qrow = (const float4*)(g_q + (n*LL + li)*DD);
    #pragma unroll
    for (int dq = 0; dq < 16; dq++) rq[dq] = qrow[dq];

    const float* kbase = g_k + n*LL*DD;
    for (int idx4 = tid; idx4 < nm*16; idx4 += 256) {
        int r = idx4 >> 4, dq = idx4 & 15;
        *(float4*)&buf[r][dq*4] = __ldg((const float4*)(kbase + (mlo+r)*DD) + dq);
    }
    __syncthreads();

    // --- band scores (4 positions per thread) ---
    float sv[4]; int vld[4];
    #pragma unroll
    for (int jj = 0; jj < 4; jj++) {
        int mo = mg*4 + jj;
        int m  = li - 32 + mo;
        vld[jj] = (m >= 0 && m < LL);
        float s = -1e30f;
        if (vld[jj]) {
            int r = m - mlo;
            s = 0.f;
            #pragma unroll 4
            for (int dq = 0; dq < 16; dq++) {
                float4 w  = was4[dq];
                float4 q  = rq[dq];
                float4 k4 = *(const float4*)&buf[r][dq*4];
                s += w.x * tanh_fast(q.x + k4.x);
                s += w.y * tanh_fast(q.y + k4.y);
                s += w.z * tanh_fast(q.z + k4.z);
                s += w.w * tanh_fast(q.w + k4.w);
            }
        }
        sv[jj] = s;
    }
    // band max per row
    float rmax = fmaxf(fmaxf(sv[0], sv[1]), fmaxf(sv[2], sv[3]));
    rmax = fmaxf(rmax, __shfl_xor_sync(0xffffffffu, rmax, 16));
    if (lane < 16) redA[wid][lane] = rmax;
    __syncthreads();
    if (tid < 16) {
        float m = redA[0][tid];
        #pragma unroll
        for (int w = 1; w < 8; w++) m = fmaxf(m, redA[w][tid]);
        rowmax[tid] = m;
    }
    __syncthreads();
    float rm = rowmax[l];
    float esum = 0.f;
    #pragma unroll
    for (int jj = 0; jj < 4; jj++) {
        float e = vld[jj] ? __expf(sv[jj] - rm) : 0.f;
        eb[l][mg*4 + jj] = e;
        esum += e;
    }
    esum += __shfl_xor_sync(0xffffffffu, esum, 16);
    if (lane < 16) redA[wid][lane] = esum;
    __syncthreads();
    if (tid < 16) {
        float s = 0.f;
        #pragma unroll
        for (int w = 0; w < 8; w++) s += redA[w][tid];
        invs[tid] = __fdividef(1.0f, s + ATTN_EPS);
    }
    // xt band load (reuse buf; all score reads of buf are done)
    const float* xtn = g_xt + n*LL*CC;
    for (int idx4 = tid; idx4 < nm*32; idx4 += 256) {
        int r = idx4 >> 5, cq = idx4 & 31;
        *(float4*)&buf[r][cq*4] = *(const float4*)(xtn + (mlo+r)*CC + cq*4);
    }
    __syncthreads();

    // --- write dense a rows (zeros outside band) ---
    float* ar = aout + (n*LL + l0)*LL;
    for (int idx = tid; idx < 16*LL; idx += 256) {
        int ll = idx >> 9, m = idx & 511;
        int mo = m - (l0 + ll - 32);
        float val = 0.f;
        if (mo >= 0 && mo < 64) val = eb[ll][mo] * invs[ll];
        ar[ll*LL + m] = val;
    }

    // --- v = a @ xt (band), residual, LN0 ---
    int c0 = mg * 8;
    int off = l0 + l - 32 - mlo;
    float acc[8];
    #pragma unroll
    for (int j = 0; j < 8; j++) acc[j] = 0.f;
    for (int mo = 0; mo < 64; mo++) {
        float w = eb[l][mo];
        int r = off + mo;
        r = min(max(r, 0), nm - 1);
        float4 xa = *(const float4*)&buf[r][c0];
        float4 xb = *(const float4*)&buf[r][c0+4];
        acc[0] += w*xa.x; acc[1] += w*xa.y; acc[2] += w*xa.z; acc[3] += w*xa.w;
        acc[4] += w*xb.x; acc[5] += w*xb.y; acc[6] += w*xb.z; acc[7] += w*xb.w;
    }
    float iv = invs[l];
    int rli = li - mlo;
    float4 ra = *(const float4*)&buf[rli][c0];
    float4 rb = *(const float4*)&buf[rli][c0+4];
    float rv[8];
    rv[0] = acc[0]*iv + ra.x; rv[1] = acc[1]*iv + ra.y;
    rv[2] = acc[2]*iv + ra.z; rv[3] = acc[3]*iv + ra.w;
    rv[4] = acc[4]*iv + rb.x; rv[5] = acc[5]*iv + rb.y;
    rv[6] = acc[6]*iv + rb.z; rv[7] = acc[7]*iv + rb.w;
    float s1 = 0.f, s2 = 0.f;
    #pragma unroll
    for (int j = 0; j < 8; j++) { s1 += rv[j]; s2 += rv[j]*rv[j]; }
    s1 += __shfl_xor_sync(0xffffffffu, s1, 16);
    s2 += __shfl_xor_sync(0xffffffffu, s2, 16);
    if (lane < 16) { redA[wid][lane] = s1; redB[wid][lane] = s2; }
    __syncthreads();
    if (tid < 16) {
        float S1 = 0.f, S2 = 0.f;
        #pragma unroll
        for (int w = 0; w < 8; w++) { S1 += redA[w][tid]; S2 += redB[w][tid]; }
        float mu  = S1 * (1.0f/CC);
        float var = S2 * (1.0f/CC) - mu*mu;
        muA[tid] = mu;
        rsA[tid] = rsqrtf(var + LN_EPS);
    }
    __syncthreads();
    float mu = muA[l], rs = rsA[l];
    float4 gv0 = *(const float4*)(g0 + c0),  gv1 = *(const float4*)(g0 + c0 + 4);
    float4 ev0 = *(const float4*)(be0 + c0), ev1 = *(const float4*)(be0 + c0 + 4);
    float* x2p = g_x2 + (n*LL + li)*CC + c0;
    float4 o0, o1;
    o0.x = (rv[0]-mu)*rs*gv0.x + ev0.x; o0.y = (rv[1]-mu)*rs*gv0.y + ev0.y;
    o0.z = (rv[2]-mu)*rs*gv0.z + ev0.z; o0.w = (rv[3]-mu)*rs*gv0.w + ev0.w;
    o1.x = (rv[4]-mu)*rs*gv1.x + ev1.x; o1.y = (rv[5]-mu)*rs*gv1.y + ev1.y;
    o1.z = (rv[6]-mu)*rs*gv1.z + ev1.z; o1.w = (rv[7]-mu)*rs*gv1.w + ev1.w;
    *(float4*)x2p = o0;
    *(float4*)(x2p + 4) = o1;
}

// ---------------- K3: H = relu(x2 @ W0 + b0); tile 64x128, 128 thr, 8x8 micro, f32x2 ----------------
__global__ __launch_bounds__(128) void k_ffn1(
    const float* __restrict__ W0, const float* __restrict__ b0) {
    __shared__ float As[16][68];
    __shared__ float Bs[16][132];
    int mb = blockIdx.x * 64, cb = blockIdx.y * 128;
    int tid = threadIdx.x;
    int tr = tid >> 4, tc = tid & 15;
    int r0 = tr * 8;
    int ca = tc * 4, cb2 = 64 + tc * 4;
    unsigned long long acc[8][4];
    #pragma unroll
    for (int i = 0; i < 8; i++)
        #pragma unroll
        for (int j = 0; j < 4; j++) acc[i][j] = 0ull;

    for (int kc = 0; kc < CC; kc += 16) {
        #pragma unroll
        for (int i = 0; i < 2; i++) {
            int idx = tid + i*128;
            int m = idx >> 2, kq = (idx & 3) * 4;
            float4 v = *(const float4*)(g_x2 + (mb+m)*CC + kc + kq);
            As[kq+0][m] = v.x; As[kq+1][m] = v.y; As[kq+2][m] = v.z; As[kq+3][m] = v.w;
        }
        #pragma unroll
        for (int i = 0; i < 4; i++) {
            int idx = tid + i*128;
            int k = idx >> 5, cq = idx & 31;
            *(float4*)&Bs[k][cq*4] = __ldg((const float4*)(W0 + (kc+k)*FF + cb + cq*4));
        }
        __syncthreads();
        #pragma unroll
        for (int k = 0; k < 16; k++) {
            float4 a0 = *(const float4*)&As[k][r0];
            float4 a1 = *(const float4*)&As[k][r0+4];
            ulonglong2 bA = *(const ulonglong2*)&Bs[k][ca];
            ulonglong2 bB = *(const ulonglong2*)&Bs[k][cb2];
            float av[8] = {a0.x,a0.y,a0.z,a0.w,a1.x,a1.y,a1.z,a1.w};
            #pragma unroll
            for (int i = 0; i < 8; i++) {
                unsigned long long ad = dup2(av[i]);
                fma2(acc[i][0], ad, bA.x);
                fma2(acc[i][1], ad, bA.y);
                fma2(acc[i][2], ad, bB.x);
                fma2(acc[i][3], ad, bB.y);
            }
        }
        __syncthreads();
    }
    float4 b0a = *(const float4*)(b0 + cb + ca);
    float4 b0b = *(const float4*)(b0 + cb + cb2);
    #pragma unroll
    for (int i = 0; i < 8; i++) {
        int row = mb + r0 + i;
        float p0,p1,p2,p3,p4,p5,p6,p7;
        unpack2(acc[i][0], p0, p1); unpack2(acc[i][1], p2, p3);
        unpack2(acc[i][2], p4, p5); unpack2(acc[i][3], p6, p7);
        float4 oa, ob;
        oa.x = fmaxf(p0 + b0a.x, 0.f); oa.y = fmaxf(p1 + b0a.y, 0.f);
        oa.z = fmaxf(p2 + b0a.z, 0.f); oa.w = fmaxf(p3 + b0a.w, 0.f);
        ob.x = fmaxf(p4 + b0b.x, 0.f); ob.y = fmaxf(p5 + b0b.y, 0.f);
        ob.z = fmaxf(p6 + b0b.z, 0.f); ob.w = fmaxf(p7 + b0b.w, 0.f);
        *(float4*)(g_H + row*FF + cb + ca)  = oa;
        *(float4*)(g_H + row*FF + cb + cb2) = ob;
    }
}

// ---------------- K4: ffn2 partials: x3_part = H[:, ks*128:(ks+1)*128] @ W1[slice] ----------------
__global__ __launch_bounds__(128) void k_ffn2p(const float* __restrict__ W1) {
    __shared__ float As[16][68];
    __shared__ float Bs[16][132];
    int mb = blockIdx.x * 64, ks = blockIdx.y;
    int kbase = ks * 128;
    int tid = threadIdx.x;
    int tr = tid >> 4, tc = tid & 15;
    int r0 = tr * 8;
    int ca = tc * 4, cb2 = 64 + tc * 4;
    unsigned long long acc[8][4];
    #pragma unroll
    for (int i = 0; i < 8; i++)
        #pragma unroll
        for (int j = 0; j < 4; j++) acc[i][j] = 0ull;

    for (int kc = 0; kc < 128; kc += 16) {
        #pragma unroll
        for (int i = 0; i < 2; i++) {
            int idx = tid + i*128;
            int m = idx >> 2, kq = (idx & 3) * 4;
            float4 v = *(const float4*)(g_H + (mb+m)*FF + kbase + kc + kq);
            As[kq+0][m] = v.x; As[kq+1][m] = v.y; As[kq+2][m] = v.z; As[kq+3][m] = v.w;
        }
        #pragma unroll
        for (int i = 0; i < 4; i++) {
            int idx = tid + i*128;
            int k = idx >> 5, cq = idx & 31;
            *(float4*)&Bs[k][cq*4] = __ldg((const float4*)(W1 + (kbase+kc+k)*CC + cq*4));
        }
        __syncthreads();
        #pragma unroll
        for (int k = 0; k < 16; k++) {
            float4 a0 = *(const float4*)&As[k][r0];
            float4 a1 = *(const float4*)&As[k][r0+4];
            ulonglong2 bA = *(const ulonglong2*)&Bs[k][ca];
            ulonglong2 bB = *(const ulonglong2*)&Bs[k][cb2];
            float av[8] = {a0.x,a0.y,a0.z,a0.w,a1.x,a1.y,a1.z,a1.w};
            #pragma unroll
            for (int i = 0; i < 8; i++) {
                unsigned long long ad = dup2(av[i]);
                fma2(acc[i][0], ad, bA.x);
                fma2(acc[i][1], ad, bA.y);
                fma2(acc[i][2], ad, bB.x);
                fma2(acc[i][3], ad, bB.y);
            }
        }
        __syncthreads();
    }
    float* pp = g_p + ks*PS;
    #pragma unroll
    for (int i = 0; i < 8; i++) {
        int row = mb + r0 + i;
        float p0,p1,p2,p3,p4,p5,p6,p7;
        unpack2(acc[i][0], p0, p1); unpack2(acc[i][1], p2, p3);
        unpack2(acc[i][2], p4, p5); unpack2(acc[i][3], p6, p7);
        *(float4*)(pp + row*CC + ca)  = make_float4(p0,p1,p2,p3);
        *(float4*)(pp + row*CC + cb2) = make_float4(p4,p5,p6,p7);
    }
}

// ---------------- K5: sum partials + b1 + x2, LN1, write transposed out ----------------
__global__ __launch_bounds__(128) void k_ln2(
    const float* __restrict__ b1, const float* __restrict__ g1,
    const float* __restrict__ be1, float* __restrict__ out) {
    __shared__ float ybuf[16][129];
    int row0 = blockIdx.x * 16;
    int n = row0 >> 9, l0 = row0 & 511;
    int tid = threadIdx.x;
    int lr = tid >> 3, cg = tid & 7;
    int c0 = cg * 16;
    int row = row0 + lr;
    float rv[16];
    #pragma unroll
    for (int q = 0; q < 4; q++) {
        int c = c0 + q*4;
        float4 a = *(const float4*)(g_p + row*CC + c);
        float4 b = *(const float4*)(g_p + PS + row*CC + c);
        float4 cpp = *(const float4*)(g_p + 2*PS + row*CC + c);
        float4 d = *(const float4*)(g_p + 3*PS + row*CC + c);
        float4 bb = *(const float4*)(b1 + c);
        float4 xx = *(const float4*)(g_x2 + row*CC + c);
        rv[q*4+0] = a.x + b.x + cpp.x + d.x + bb.x + xx.x;
        rv[q*4+1] = a.y + b.y + cpp.y + d.y + bb.y + xx.y;
        rv[q*4+2] = a.z + b.z + cpp.z + d.z + bb.z + xx.z;
        rv[q*4+3] = a.w + b.w + cpp.w + d.w + bb.w + xx.w;
    }
    float s1 = 0.f, s2 = 0.f;
    #pragma unroll
    for (int j = 0; j < 16; j++) { s1 += rv[j]; s2 += rv[j]*rv[j]; }
    #pragma unroll
    for (int o = 1; o < 8; o <<= 1) {
        s1 += __shfl_xor_sync(0xffffffffu, s1, o);
        s2 += __shfl_xor_sync(0xffffffffu, s2, o);
    }
    float mu  = s1 * (1.0f/CC);
    float var = s2 * (1.0f/CC) - mu*mu;
    float inv = rsqrtf(var + LN_EPS);
    #pragma unroll
    for (int q = 0; q < 4; q++) {
        int c = c0 + q*4;
        float4 gv = *(const float4*)(g1 + c);
        float4 ev = *(const float4*)(be1 + c);
        ybuf[lr][c+0] = (rv[q*4+0]-mu)*inv*gv.x + ev.x;
        ybuf[lr][c+1] = (rv[q*4+1]-mu)*inv*gv.y + ev.y;
        ybuf[lr][c+2] = (rv[q*4+2]-mu)*inv*gv.z + ev.z;
        ybuf[lr][c+3] = (rv[q*4+3]-mu)*inv*gv.w + ev.w;
    }
    __syncthreads();
    float* ob = out + n*CC*LL + l0;
    for (int idx = tid; idx < 16*CC; idx += 128) {
        int c = idx >> 4, lw = idx & 15;
        ob[c*LL + lw] = ybuf[lw][c];
    }
}

// ---------------- launch ----------------
extern "C" void kernel_launch(void* const* d_in, const int* in_sizes, int n_in,
                              void* d_out, int out_size) {
    const float* x   = (const float*)d_in[0];
    const float* Wx  = (const float*)d_in[1];
    const float* Wt  = (const float*)d_in[2];
    const float* bh  = (const float*)d_in[3];
    const float* Wa  = (const float*)d_in[4];
    // d_in[5] = ba: cancels in softmax; unused
    const float* W0  = (const float*)d_in[6];
    const float* b0  = (const float*)d_in[7];
    const float* W1  = (const float*)d_in[8];
    const float* b1  = (const float*)d_in[9];
    const float* g0  = (const float*)d_in[10];
    const float* be0 = (const float*)d_in[11];
    const float* g1  = (const float*)d_in[12];
    const float* be1 = (const float*)d_in[13];
    float* out  = (float*)d_out;
    float* aout = out + NN*CC*LL;  // second output: a (N,L,L)

    k_prep        <<<dim3(LL/64, NN), 256>>>(x, Wt, Wx, bh);
    k_scores_fused<<<dim3(LL/16, NN), 256>>>(Wa, g0, be0, aout);
    k_ffn1        <<<dim3(NN*LL/64, FF/128), 128>>>(W0, b0);
    k_ffn2p       <<<dim3(NN*LL/64, 4), 128>>>(W1);
    k_ln2         <<<NN*LL/16, 128>>>(b1, g1, be1, out);
}

// round 3
// speedup vs baseline: 2.0928x; 1.1463x over previous
#include <cuda_runtime.h>

#define NN 8
#define CC 128
#define LL 512
#define DD 64
#define FF 512
#define LN_EPS 1e-5f
#define ATTN_EPS 1e-6f

// ---------------- scratch (static device globals; no allocation) ----------------
__device__ float g_xt[NN*LL*CC];   // (n,l,c)  2MB
__device__ float g_q [NN*LL*DD];   // q + bh   1MB
__device__ float g_k [NN*LL*DD];   // k        1MB
__device__ float g_x2[NN*LL*CC];   // post-LN0 2MB

__device__ __forceinline__ float tanh_fast(float x) {
    float e = __expf(-2.0f * fabsf(x));
    float t = __fdividef(1.0f - e, 1.0f + e);
    return copysignf(t, x);
}
__device__ __forceinline__ void fma2(unsigned long long& acc, unsigned long long a,
                                     unsigned long long b) {
    asm("fma.rn.f32x2 %0, %1, %2, %0;" : "+l"(acc) : "l"(a), "l"(b));
}
__device__ __forceinline__ unsigned long long dup2(float a) {
    unsigned long long r;
    asm("mov.b64 %0, {%1, %1};" : "=l"(r) : "f"(a));
    return r;
}
__device__ __forceinline__ void unpack2(unsigned long long v, float& lo, float& hi) {
    asm("mov.b64 {%0, %1}, %2;" : "=f"(lo), "=f"(hi) : "l"(v));
}
__device__ __forceinline__ void cp16(float* s, const float* g) {
    unsigned sa = (unsigned)__cvta_generic_to_shared(s);
    asm volatile("cp.async.cg.shared.global [%0], [%1], 16;" :: "r"(sa), "l"(g) : "memory");
}
__device__ __forceinline__ void cp_commit() {
    asm volatile("cp.async.commit_group;" ::: "memory");
}
__device__ __forceinline__ void cp_wait0() {
    asm volatile("cp.async.wait_group 0;" ::: "memory");
}

// ---------------- K1: transpose x -> xt, q'=xt@Wt+bh, k=xt@Wx; 32 rows/block ----------------
__global__ __launch_bounds__(256) void k_prep(
    const float* __restrict__ x, const float* __restrict__ Wt,
    const float* __restrict__ Wx, const float* __restrict__ bh) {
    __shared__ float xs[CC][33];
    int n = blockIdx.y, l0 = blockIdx.x * 32;
    const float* xp = x + n*CC*LL + l0;
    for (int i = 0; i < 16; i++) {
        int idx = threadIdx.x + i*256;
        int c = idx >> 5, l = idx & 31;
        xs[c][l] = xp[c*LL + l];
    }
    __syncthreads();
    float* xtp = g_xt + (n*LL + l0)*CC;
    for (int i = 0; i < 16; i++) {
        int idx = threadIdx.x + i*256;
        int l = idx >> 7, c = idx & 127;
        xtp[l*CC + c] = xs[c][l];
    }
    int l  = threadIdx.x >> 3;
    int d0 = (threadIdx.x & 7) * 8;
    float aq[8], ak[8];
    #pragma unroll
    for (int j = 0; j < 8; j++) { aq[j] = bh[d0+j]; ak[j] = 0.f; }
    for (int c = 0; c < CC; c++) {
        float xv = xs[c][l];
        #pragma unroll
        for (int j4 = 0; j4 < 2; j4++) {
            float4 wt = __ldg((const float4*)(Wt + c*DD + d0) + j4);
            float4 wx = __ldg((const float4*)(Wx + c*DD + d0) + j4);
            aq[j4*4+0] += xv*wt.x; aq[j4*4+1] += xv*wt.y;
            aq[j4*4+2] += xv*wt.z; aq[j4*4+3] += xv*wt.w;
            ak[j4*4+0] += xv*wx.x; ak[j4*4+1] += xv*wx.y;
            ak[j4*4+2] += xv*wx.z; ak[j4*4+3] += xv*wx.w;
        }
    }
    float* qp = g_q + (n*LL + l0 + l)*DD + d0;
    float* kp = g_k + (n*LL + l0 + l)*DD + d0;
    #pragma unroll
    for (int j = 0; j < 8; j++) { qp[j] = aq[j]; kp[j] = ak[j]; }
}

// ---------------- K2: band scores + a write + attn-apply + LN0 (unchanged from R2) ----------------
__global__ __launch_bounds__(256) void k_scores_fused(
    const float* __restrict__ Wa, const float* __restrict__ g0,
    const float* __restrict__ be0, float* __restrict__ aout) {
    __shared__ float  buf[79][132];
    __shared__ float  eb[16][65];
    __shared__ float4 was4[16];
    __shared__ float  redA[8][16];
    __shared__ float  redB[8][16];
    __shared__ float  rowmax[16], invs[16], muA[16], rsA[16];

    int n = blockIdx.y, l0 = blockIdx.x * 16;
    int tid = threadIdx.x;
    int l = tid & 15, mg = tid >> 4;
    int li = l0 + l;
    int wid = tid >> 5, lane = tid & 31;

    int mlo = l0 - 32; if (mlo < 0) mlo = 0;
    int mhi = l0 + 46; if (mhi > LL-1) mhi = LL-1;
    int nm  = mhi - mlo + 1;

    if (tid < 16) was4[tid] = *(const float4*)(Wa + tid*4);

    float4 rq[16];
    const float4* qrow = (const float4*)(g_q + (n*LL + li)*DD);
    #pragma unroll
    for (int dq = 0; dq < 16; dq++) rq[dq] = qrow[dq];

    const float* kbase = g_k + n*LL*DD;
    for (int idx4 = tid; idx4 < nm*16; idx4 += 256) {
        int r = idx4 >> 4, dq = idx4 & 15;
        *(float4*)&buf[r][dq*4] = __ldg((const float4*)(kbase + (mlo+r)*DD) + dq);
    }
    __syncthreads();

    float sv[4]; int vld[4];
    #pragma unroll
    for (int jj = 0; jj < 4; jj++) {
        int mo = mg*4 + jj;
        int m  = li - 32 + mo;
        vld[jj] = (m >= 0 && m < LL);
        float s = -1e30f;
        if (vld[jj]) {
            int r = m - mlo;
            s = 0.f;
            #pragma unroll 4
            for (int dq = 0; dq < 16; dq++) {
                float4 w  = was4[dq];
                float4 q  = rq[dq];
                float4 k4 = *(const float4*)&buf[r][dq*4];
                s += w.x * tanh_fast(q.x + k4.x);
                s += w.y * tanh_fast(q.y + k4.y);
                s += w.z * tanh_fast(q.z + k4.z);
                s += w.w * tanh_fast(q.w + k4.w);
            }
        }
        sv[jj] = s;
    }
    float rmax = fmaxf(fmaxf(sv[0], sv[1]), fmaxf(sv[2], sv[3]));
    rmax = fmaxf(rmax, __shfl_xor_sync(0xffffffffu, rmax, 16));
    if (lane < 16) redA[wid][lane] = rmax;
    __syncthreads();
    if (tid < 16) {
        float m = redA[0][tid];
        #pragma unroll
        for (int w = 1; w < 8; w++) m = fmaxf(m, redA[w][tid]);
        rowmax[tid] = m;
    }
    __syncthreads();
    float rm = rowmax[l];
    float esum = 0.f;
    #pragma unroll
    for (int jj = 0; jj < 4; jj++) {
        float e = vld[jj] ? __expf(sv[jj] - rm) : 0.f;
        eb[l][mg*4 + jj] = e;
        esum += e;
    }
    esum += __shfl_xor_sync(0xffffffffu, esum, 16);
    if (lane < 16) redA[wid][lane] = esum;
    __syncthreads();
    if (tid < 16) {
        float s = 0.f;
        #pragma unroll
        for (int w = 0; w < 8; w++) s += redA[w][tid];
        invs[tid] = __fdividef(1.0f, s + ATTN_EPS);
    }
    const float* xtn = g_xt + n*LL*CC;
    for (int idx4 = tid; idx4 < nm*32; idx4 += 256) {
        int r = idx4 >> 5, cq = idx4 & 31;
        *(float4*)&buf[r][cq*4] = *(const float4*)(xtn + (mlo+r)*CC + cq*4);
    }
    __syncthreads();

    float* ar = aout + (n*LL + l0)*LL;
    for (int idx = tid; idx < 16*LL; idx += 256) {
        int ll = idx >> 9, m = idx & 511;
        int mo = m - (l0 + ll - 32);
        float val = 0.f;
        if (mo >= 0 && mo < 64) val = eb[ll][mo] * invs[ll];
        ar[ll*LL + m] = val;
    }

    int c0 = mg * 8;
    int off = l0 + l - 32 - mlo;
    float acc[8];
    #pragma unroll
    for (int j = 0; j < 8; j++) acc[j] = 0.f;
    for (int mo = 0; mo < 64; mo++) {
        float w = eb[l][mo];
        int r = off + mo;
        r = min(max(r, 0), nm - 1);
        float4 xa = *(const float4*)&buf[r][c0];
        float4 xb = *(const float4*)&buf[r][c0+4];
        acc[0] += w*xa.x; acc[1] += w*xa.y; acc[2] += w*xa.z; acc[3] += w*xa.w;
        acc[4] += w*xb.x; acc[5] += w*xb.y; acc[6] += w*xb.z; acc[7] += w*xb.w;
    }
    float iv = invs[l];
    int rli = li - mlo;
    float4 ra = *(const float4*)&buf[rli][c0];
    float4 rb = *(const float4*)&buf[rli][c0+4];
    float rv[8];
    rv[0] = acc[0]*iv + ra.x; rv[1] = acc[1]*iv + ra.y;
    rv[2] = acc[2]*iv + ra.z; rv[3] = acc[3]*iv + ra.w;
    rv[4] = acc[4]*iv + rb.x; rv[5] = acc[5]*iv + rb.y;
    rv[6] = acc[6]*iv + rb.z; rv[7] = acc[7]*iv + rb.w;
    float s1 = 0.f, s2 = 0.f;
    #pragma unroll
    for (int j = 0; j < 8; j++) { s1 += rv[j]; s2 += rv[j]*rv[j]; }
    s1 += __shfl_xor_sync(0xffffffffu, s1, 16);
    s2 += __shfl_xor_sync(0xffffffffu, s2, 16);
    if (lane < 16) { redA[wid][lane] = s1; redB[wid][lane] = s2; }
    __syncthreads();
    if (tid < 16) {
        float S1 = 0.f, S2 = 0.f;
        #pragma unroll
        for (int w = 0; w < 8; w++) { S1 += redA[w][tid]; S2 += redB[w][tid]; }
        float mu  = S1 * (1.0f/CC);
        float var = S2 * (1.0f/CC) - mu*mu;
        muA[tid] = mu;
        rsA[tid] = rsqrtf(var + LN_EPS);
    }
    __syncthreads();
    float mu = muA[l], rs = rsA[l];
    float4 gv0 = *(const float4*)(g0 + c0),  gv1 = *(const float4*)(g0 + c0 + 4);
    float4 ev0 = *(const float4*)(be0 + c0), ev1 = *(const float4*)(be0 + c0 + 4);
    float* x2p = g_x2 + (n*LL + li)*CC + c0;
    float4 o0, o1;
    o0.x = (rv[0]-mu)*rs*gv0.x + ev0.x; o0.y = (rv[1]-mu)*rs*gv0.y + ev0.y;
    o0.z = (rv[2]-mu)*rs*gv0.z + ev0.z; o0.w = (rv[3]-mu)*rs*gv0.w + ev0.w;
    o1.x = (rv[4]-mu)*rs*gv1.x + ev1.x; o1.y = (rv[5]-mu)*rs*gv1.y + ev1.y;
    o1.z = (rv[6]-mu)*rs*gv1.z + ev1.z; o1.w = (rv[7]-mu)*rs*gv1.w + ev1.w;
    *(float4*)x2p = o0;
    *(float4*)(x2p + 4) = o1;
}

// ---------------- K3: fused FFN (H = relu(x2@W0+b0); x3 = H@W1+b1; LN1; transposed out) ----------------
// grid = 128 blocks (32-row stripes), 256 threads, dynamic smem ~158KB.
#define X2S_OFF 0
#define HT_OFF  4608            // X2S = 128 x 36
#define BS_OFF  23040           // HT  = 512 x 36
#define BS_STRIDE 8192          // BS  = 2 x 8192 (P1: 16x512; P2: 32x128)

__global__ __launch_bounds__(256) void k_ffn(
    const float* __restrict__ W0, const float* __restrict__ b0,
    const float* __restrict__ W1, const float* __restrict__ b1,
    const float* __restrict__ g1, const float* __restrict__ be1,
    float* __restrict__ out) {
    extern __shared__ float sm[];
    float* X2S = sm + X2S_OFF;     // [c=128][r=32 pad36]
    float* HT  = sm + HT_OFF;      // [k2=512][r=32 pad36]; later ybuf[32][132]
    float* BS  = sm + BS_OFF;

    int mb = blockIdx.x * 32;
    int n = mb >> 9, l0 = mb & 511;
    int tid = threadIdx.x;

    // load x2 stripe into X2S (k-major: [c][r])
    #pragma unroll
    for (int i = 0; i < 4; i++) {
        int idx = tid + i*256;            // 1024 float4s
        int r = idx >> 5, c4 = (idx & 31) * 4;
        float4 v = *(const float4*)(g_x2 + (mb + r)*CC + c4);
        X2S[(c4+0)*36 + r] = v.x; X2S[(c4+1)*36 + r] = v.y;
        X2S[(c4+2)*36 + r] = v.z; X2S[(c4+3)*36 + r] = v.w;
    }

    // ================= Phase 1: H = relu(x2 @ W0 + b0), full 32x512 =================
    int r0 = (tid & 3) * 8;        // 4 row-groups of 8
    int c0 = (tid >> 2) * 8;       // 64 col-groups of 8 -> 512
    unsigned long long hacc[8][4];
    #pragma unroll
    for (int j = 0; j < 8; j++)
        #pragma unroll
        for (int rp = 0; rp < 4; rp++) hacc[j][rp] = 0ull;

    int buf = 0;
    // preload chunk 0 (k rows 0..15 of W0, all 512 cols)
    #pragma unroll
    for (int i = 0; i < 8; i++) {
        int idx = tid + i*256;            // 2048 float4s
        int k = idx >> 7, c4 = (idx & 127) * 4;
        cp16(&BS[k*512 + c4], W0 + k*FF + c4);
    }
    cp_commit();
    for (int kc = 0; kc < 8; kc++) {
        cp_wait0(); __syncthreads();
        if (kc < 7) {
            int kb = (kc+1)*16;
            float* dst = &BS[(buf^1)*BS_STRIDE];
            #pragma unroll
            for (int i = 0; i < 8; i++) {
                int idx = tid + i*256;
                int k = idx >> 7, c4 = (idx & 127) * 4;
                cp16(dst + k*512 + c4, W0 + (kb + k)*FF + c4);
            }
            cp_commit();
        }
        const float* bsb = &BS[buf*BS_STRIDE];
        #pragma unroll
        for (int k = 0; k < 16; k++) {
            int kg = kc*16 + k;
            ulonglong2 u0 = *(const ulonglong2*)&X2S[kg*36 + r0];
            ulonglong2 u1 = *(const ulonglong2*)&X2S[kg*36 + r0 + 4];
            float4 bA = *(const float4*)(bsb + k*512 + c0);
            float4 bB = *(const float4*)(bsb + k*512 + c0 + 4);
            float bv[8] = {bA.x,bA.y,bA.z,bA.w,bB.x,bB.y,bB.z,bB.w};
            #pragma unroll
            for (int j = 0; j < 8; j++) {
                unsigned long long bd = dup2(bv[j]);
                fma2(hacc[j][0], bd, u0.x);
                fma2(hacc[j][1], bd, u0.y);
                fma2(hacc[j][2], bd, u1.x);
                fma2(hacc[j][3], bd, u1.y);
            }
        }
        __syncthreads();
        buf ^= 1;
    }
    // epilogue P1: relu + b0 -> HT[k2=c][r]
    #pragma unroll
    for (int j = 0; j < 8; j++) {
        float bj = __ldg(b0 + c0 + j);
        float* dst = &HT[(c0+j)*36 + r0];
        #pragma unroll
        for (int rp = 0; rp < 4; rp++) {
            float p0, p1; unpack2(hacc[j][rp], p0, p1);
            dst[rp*2+0] = fmaxf(p0 + bj, 0.f);
            dst[rp*2+1] = fmaxf(p1 + bj, 0.f);
        }
    }
    __syncthreads();

    // ================= Phase 2: x3 = H @ W1 (K=512), 32x128 =================
    int r2 = (tid & 3) * 8;
    int c2 = (tid >> 2) * 2;       // 64 col-groups of 2 -> 128
    unsigned long long xacc[2][4];
    #pragma unroll
    for (int j = 0; j < 2; j++)
        #pragma unroll
        for (int rp = 0; rp < 4; rp++) xacc[j][rp] = 0ull;

    buf = 0;
    #pragma unroll
    for (int i = 0; i < 4; i++) {
        int idx = tid + i*256;            // 1024 float4s: [32][128]
        int k = idx >> 5, c4 = (idx & 31) * 4;
        cp16(&BS[k*128 + c4], W1 + k*CC + c4);
    }
    cp_commit();
    for (int kc = 0; kc < 16; kc++) {
        cp_wait0(); __syncthreads();
        if (kc < 15) {
            int kb = (kc+1)*32;
            float* dst = &BS[(buf^1)*BS_STRIDE];
            #pragma unroll
            for (int i = 0; i < 4; i++) {
                int idx = tid + i*256;
                int k = idx >> 5, c4 = (idx & 31) * 4;
                cp16(dst + k*128 + c4, W1 + (kb + k)*CC + c4);
            }
            cp_commit();
        }
        const float* bsb = &BS[buf*BS_STRIDE];
        #pragma unroll
        for (int k = 0; k < 32; k++) {
            int kg = kc*32 + k;
            ulonglong2 u0 = *(const ulonglong2*)&HT[kg*36 + r2];
            ulonglong2 u1 = *(const ulonglong2*)&HT[kg*36 + r2 + 4];
            float2 b2 = *(const float2*)(bsb + k*128 + c2);
            unsigned long long bd0 = dup2(b2.x);
            unsigned long long bd1 = dup2(b2.y);
            fma2(xacc[0][0], bd0, u0.x); fma2(xacc[0][1], bd0, u0.y);
            fma2(xacc[0][2], bd0, u1.x); fma2(xacc[0][3], bd0, u1.y);
            fma2(xacc[1][0], bd1, u0.x); fma2(xacc[1][1], bd1, u0.y);
            fma2(xacc[1][2], bd1, u1.x); fma2(xacc[1][3], bd1, u1.y);
        }
        __syncthreads();
        buf ^= 1;
    }

    // epilogue: rv = x3 + b1 + x2 -> ybuf (reuse HT as [32][132])
    float* YB = HT;
    #pragma unroll
    for (int j = 0; j < 2; j++) {
        float bj = __ldg(b1 + c2 + j);
        #pragma unroll
        for (int rp = 0; rp < 4; rp++) {
            float v0, v1; unpack2(xacc[j][rp], v0, v1);
            int ra = r2 + rp*2;
            v0 += bj + X2S[(c2+j)*36 + ra];
            v1 += bj + X2S[(c2+j)*36 + ra + 1];
            YB[(ra)*132 + c2 + j]   = v0;
            YB[(ra+1)*132 + c2 + j] = v1;
        }
    }
    __syncthreads();

    // LN1 per row (warp w handles rows 4w..4w+3) + scale/shift
    int wid = tid >> 5, lane = tid & 31;
    #pragma unroll
    for (int i = 0; i < 4; i++) {
        int row = wid*4 + i;
        float4 v = *(const float4*)&YB[row*132 + lane*4];
        float s1 = v.x + v.y + v.z + v.w;
        float s2 = v.x*v.x + v.y*v.y + v.z*v.z + v.w*v.w;
        #pragma unroll
        for (int o = 16; o > 0; o >>= 1) {
            s1 += __shfl_xor_sync(0xffffffffu, s1, o);
            s2 += __shfl_xor_sync(0xffffffffu, s2, o);
        }
        float mu  = s1 * (1.0f/CC);
        float var = s2 * (1.0f/CC) - mu*mu;
        float inv = rsqrtf(var + LN_EPS);
        float4 g = __ldg((const float4*)(g1 + lane*4));
        float4 e = __ldg((const float4*)(be1 + lane*4));
        v.x = (v.x - mu)*inv*g.x + e.x;
        v.y = (v.y - mu)*inv*g.y + e.y;
        v.z = (v.z - mu)*inv*g.z + e.z;
        v.w = (v.w - mu)*inv*g.w + e.w;
        *(float4*)&YB[row*132 + lane*4] = v;
    }
    __syncthreads();

    // transposed write: out[n][c][l0+l]
    float* ob = out + n*CC*LL + l0;
    #pragma unroll
    for (int i = 0; i < 16; i++) {
        int idx = tid + i*256;            // 4096
        int c = idx >> 5, l = idx & 31;
        ob[c*LL + l] = YB[l*132 + c];
    }
}

// ---------------- launch ----------------
extern "C" void kernel_launch(void* const* d_in, const int* in_sizes, int n_in,
                              void* d_out, int out_size) {
    const float* x   = (const float*)d_in[0];
    const float* Wx  = (const float*)d_in[1];
    const float* Wt  = (const float*)d_in[2];
    const float* bh  = (const float*)d_in[3];
    const float* Wa  = (const float*)d_in[4];
    // d_in[5] = ba: cancels in softmax; unused
    const float* W0  = (const float*)d_in[6];
    const float* b0  = (const float*)d_in[7];
    const float* W1  = (const float*)d_in[8];
    const float* b1  = (const float*)d_in[9];
    const float* g0  = (const float*)d_in[10];
    const float* be0 = (const float*)d_in[11];
    const float* g1  = (const float*)d_in[12];
    const float* be1 = (const float*)d_in[13];
    float* out  = (float*)d_out;
    float* aout = out + NN*CC*LL;  // second output: a (N,L,L)

    static int smem_set = 0;
    const int FFN_SMEM = (23040 + 2*8192) * 4;   // 158,208 bytes
    if (!smem_set) {
        cudaFuncSetAttribute(k_ffn, cudaFuncAttributeMaxDynamicSharedMemorySize, FFN_SMEM);
        smem_set = 1;
    }

    k_prep        <<<dim3(LL/32, NN), 256>>>(x, Wt, Wx, bh);
    k_scores_fused<<<dim3(LL/16, NN), 256>>>(Wa, g0, be0, aout);
    k_ffn         <<<NN*LL/32, 256, FFN_SMEM>>>(W0, b0, W1, b1, g1, be1, out);
}

// round 4
// speedup vs baseline: 2.7326x; 1.3057x over previous
#include <cuda_runtime.h>

#define NN 8
#define CC 128
#define LL 512
#define DD 64
#define FF 512
#define LN_EPS 1e-5f
#define ATTN_EPS 1e-6f

// ---------------- scratch (static device globals; no allocation) ----------------
__device__ float g_xt[NN*LL*CC];   // (n,l,c)  2MB
__device__ float g_q [NN*LL*DD];   // q + bh   1MB
__device__ float g_k [NN*LL*DD];   // k        1MB
__device__ float g_x2[NN*LL*CC];   // post-LN0 2MB

__device__ __forceinline__ float tanh_fast(float x) {
    float e = __expf(-2.0f * fabsf(x));
    float t = __fdividef(1.0f - e, 1.0f + e);
    return copysignf(t, x);
}
__device__ __forceinline__ void fma2(unsigned long long& acc, unsigned long long a,
                                     unsigned long long b) {
    asm("fma.rn.f32x2 %0, %1, %2, %0;" : "+l"(acc) : "l"(a), "l"(b));
}
__device__ __forceinline__ unsigned long long dup2(float a) {
    unsigned long long r;
    asm("mov.b64 %0, {%1, %1};" : "=l"(r) : "f"(a));
    return r;
}
__device__ __forceinline__ void unpack2(unsigned long long v, float& lo, float& hi) {
    asm("mov.b64 {%0, %1}, %2;" : "=f"(lo), "=f"(hi) : "l"(v));
}
__device__ __forceinline__ void cp16(float* s, const float* g) {
    unsigned sa = (unsigned)__cvta_generic_to_shared(s);
    asm volatile("cp.async.cg.shared.global [%0], [%1], 16;" :: "r"(sa), "l"(g) : "memory");
}
__device__ __forceinline__ void cp_commit() {
    asm volatile("cp.async.commit_group;" ::: "memory");
}
__device__ __forceinline__ void cp_wait0() {
    asm volatile("cp.async.wait_group 0;" ::: "memory");
}

// ---------------- K1: smem-staged GEMM: xt transpose + [q|k] = xt @ [Wt|Wx] (+bh) ----------------
// 128 blocks (32 l-rows each), 256 threads, 84KB dyn smem.
__global__ __launch_bounds__(256) void k_prep(
    const float* __restrict__ x, const float* __restrict__ Wt,
    const float* __restrict__ Wx, const float* __restrict__ bh) {
    extern __shared__ float sm[];
    float* XS = sm;            // [c=128][l, pad 36]
    float* WS = sm + 128*36;   // [c=128][128]: cols 0-63 Wt, 64-127 Wx

    int n = blockIdx.y, l0 = blockIdx.x * 32;
    int tid = threadIdx.x;

    const float* xp = x + n*CC*LL + l0;
    #pragma unroll
    for (int i = 0; i < 16; i++) {
        int idx = tid + i*256;
        int c = idx >> 5, l = idx & 31;
        XS[c*36 + l] = xp[c*LL + l];
    }
    #pragma unroll
    for (int i = 0; i < 8; i++) {
        int idx = tid + i*256;           // 2048 float4 slots per matrix
        int row = idx >> 4, d4 = (idx & 15) * 4;
        *(float4*)&WS[row*128 + d4]      = __ldg((const float4*)(Wt + row*DD + d4));
        *(float4*)&WS[row*128 + 64 + d4] = __ldg((const float4*)(Wx + row*DD + d4));
    }
    __syncthreads();

    // transpose write g_xt
    float* xtp = g_xt + (n*LL + l0)*CC;
    #pragma unroll
    for (int i = 0; i < 16; i++) {
        int idx = tid + i*256;
        int l = idx >> 7, c = idx & 127;
        xtp[l*CC + c] = XS[c*36 + l];
    }

    // GEMM 32 x 128 x 128 from smem; micro 4 rows x 4 cols, FFMA2 over row pairs
    int r0 = (tid >> 5) * 4;       // 8 row-groups
    int c0 = (tid & 31) * 4;       // 32 col-groups
    unsigned long long acc[4][2];
    #pragma unroll
    for (int j = 0; j < 4; j++) { acc[j][0] = 0ull; acc[j][1] = 0ull; }

    #pragma unroll 4
    for (int k = 0; k < CC; k++) {
        ulonglong2 a2 = *(const ulonglong2*)&XS[k*36 + r0];   // broadcast within warp
        float4 b = *(const float4*)&WS[k*128 + c0];           // conflict-free LDS.128
        unsigned long long bd0 = dup2(b.x), bd1 = dup2(b.y);
        unsigned long long bd2 = dup2(b.z), bd3 = dup2(b.w);
        fma2(acc[0][0], bd0, a2.x); fma2(acc[0][1], bd0, a2.y);
        fma2(acc[1][0], bd1, a2.x); fma2(acc[1][1], bd1, a2.y);
        fma2(acc[2][0], bd2, a2.x); fma2(acc[2][1], bd2, a2.y);
        fma2(acc[3][0], bd3, a2.x); fma2(acc[3][1], bd3, a2.y);
    }

    bool isq = (c0 < 64);
    int d0 = isq ? c0 : c0 - 64;
    float4 bhv = make_float4(0.f, 0.f, 0.f, 0.f);
    if (isq) bhv = *(const float4*)(bh + c0);
    float* base = isq ? g_q : g_k;
    #pragma unroll
    for (int rp = 0; rp < 2; rp++) {
        float v0[4], v1[4];
        #pragma unroll
        for (int j = 0; j < 4; j++) unpack2(acc[j][rp], v0[j], v1[j]);
        int row = n*LL + l0 + r0 + rp*2;
        float4 o0 = make_float4(v0[0]+bhv.x, v0[1]+bhv.y, v0[2]+bhv.z, v0[3]+bhv.w);
        float4 o1 = make_float4(v1[0]+bhv.x, v1[1]+bhv.y, v1[2]+bhv.z, v1[3]+bhv.w);
        *(float4*)(base + row*DD + d0)     = o0;
        *(float4*)(base + (row+1)*DD + d0) = o1;
    }
}

// ---------------- K2: band scores + a write + attn-apply + LN0 (unchanged) ----------------
__global__ __launch_bounds__(256) void k_scores_fused(
    const float* __restrict__ Wa, const float* __restrict__ g0,
    const float* __restrict__ be0, float* __restrict__ aout) {
    __shared__ float  buf[79][132];
    __shared__ float  eb[16][65];
    __shared__ float4 was4[16];
    __shared__ float  redA[8][16];
    __shared__ float  redB[8][16];
    __shared__ float  rowmax[16], invs[16], muA[16], rsA[16];

    int n = blockIdx.y, l0 = blockIdx.x * 16;
    int tid = threadIdx.x;
    int l = tid & 15, mg = tid >> 4;
    int li = l0 + l;
    int wid = tid >> 5, lane = tid & 31;

    int mlo = l0 - 32; if (mlo < 0) mlo = 0;
    int mhi = l0 + 46; if (mhi > LL-1) mhi = LL-1;
    int nm  = mhi - mlo + 1;

    if (tid < 16) was4[tid] = *(const float4*)(Wa + tid*4);

    float4 rq[16];
    const float4* qrow = (const float4*)(g_q + (n*LL + li)*DD);
    #pragma unroll
    for (int dq = 0; dq < 16; dq++) rq[dq] = qrow[dq];

    const float* kbase = g_k + n*LL*DD;
    for (int idx4 = tid; idx4 < nm*16; idx4 += 256) {
        int r = idx4 >> 4, dq = idx4 & 15;
        *(float4*)&buf[r][dq*4] = __ldg((const float4*)(kbase + (mlo+r)*DD) + dq);
    }
    __syncthreads();

    float sv[4]; int vld[4];
    #pragma unroll
    for (int jj = 0; jj < 4; jj++) {
        int mo = mg*4 + jj;
        int m  = li - 32 + mo;
        vld[jj] = (m >= 0 && m < LL);
        float s = -1e30f;
        if (vld[jj]) {
            int r = m - mlo;
            s = 0.f;
            #pragma unroll 4
            for (int dq = 0; dq < 16; dq++) {
                float4 w  = was4[dq];
                float4 q  = rq[dq];
                float4 k4 = *(const float4*)&buf[r][dq*4];
                s += w.x * tanh_fast(q.x + k4.x);
                s += w.y * tanh_fast(q.y + k4.y);
                s += w.z * tanh_fast(q.z + k4.z);
                s += w.w * tanh_fast(q.w + k4.w);
            }
        }
        sv[jj] = s;
    }
    float rmax = fmaxf(fmaxf(sv[0], sv[1]), fmaxf(sv[2], sv[3]));
    rmax = fmaxf(rmax, __shfl_xor_sync(0xffffffffu, rmax, 16));
    if (lane < 16) redA[wid][lane] = rmax;
    __syncthreads();
    if (tid < 16) {
        float m = redA[0][tid];
        #pragma unroll
        for (int w = 1; w < 8; w++) m = fmaxf(m, redA[w][tid]);
        rowmax[tid] = m;
    }
    __syncthreads();
    float rm = rowmax[l];
    float esum = 0.f;
    #pragma unroll
    for (int jj = 0; jj < 4; jj++) {
        float e = vld[jj] ? __expf(sv[jj] - rm) : 0.f;
        eb[l][mg*4 + jj] = e;
        esum += e;
    }
    esum += __shfl_xor_sync(0xffffffffu, esum, 16);
    if (lane < 16) redA[wid][lane] = esum;
    __syncthreads();
    if (tid < 16) {
        float s = 0.f;
        #pragma unroll
        for (int w = 0; w < 8; w++) s += redA[w][tid];
        invs[tid] = __fdividef(1.0f, s + ATTN_EPS);
    }
    const float* xtn = g_xt + n*LL*CC;
    for (int idx4 = tid; idx4 < nm*32; idx4 += 256) {
        int r = idx4 >> 5, cq = idx4 & 31;
        *(float4*)&buf[r][cq*4] = *(const float4*)(xtn + (mlo+r)*CC + cq*4);
    }
    __syncthreads();

    float* ar = aout + (n*LL + l0)*LL;
    for (int idx = tid; idx < 16*LL; idx += 256) {
        int ll = idx >> 9, m = idx & 511;
        int mo = m - (l0 + ll - 32);
        float val = 0.f;
        if (mo >= 0 && mo < 64) val = eb[ll][mo] * invs[ll];
        ar[ll*LL + m] = val;
    }

    int c0 = mg * 8;
    int off = l0 + l - 32 - mlo;
    float acc[8];
    #pragma unroll
    for (int j = 0; j < 8; j++) acc[j] = 0.f;
    for (int mo = 0; mo < 64; mo++) {
        float w = eb[l][mo];
        int r = off + mo;
        r = min(max(r, 0), nm - 1);
        float4 xa = *(const float4*)&buf[r][c0];
        float4 xb = *(const float4*)&buf[r][c0+4];
        acc[0] += w*xa.x; acc[1] += w*xa.y; acc[2] += w*xa.z; acc[3] += w*xa.w;
        acc[4] += w*xb.x; acc[5] += w*xb.y; acc[6] += w*xb.z; acc[7] += w*xb.w;
    }
    float iv = invs[l];
    int rli = li - mlo;
    float4 ra = *(const float4*)&buf[rli][c0];
    float4 rb = *(const float4*)&buf[rli][c0+4];
    float rv[8];
    rv[0] = acc[0]*iv + ra.x; rv[1] = acc[1]*iv + ra.y;
    rv[2] = acc[2]*iv + ra.z; rv[3] = acc[3]*iv + ra.w;
    rv[4] = acc[4]*iv + rb.x; rv[5] = acc[5]*iv + rb.y;
    rv[6] = acc[6]*iv + rb.z; rv[7] = acc[7]*iv + rb.w;
    float s1 = 0.f, s2 = 0.f;
    #pragma unroll
    for (int j = 0; j < 8; j++) { s1 += rv[j]; s2 += rv[j]*rv[j]; }
    s1 += __shfl_xor_sync(0xffffffffu, s1, 16);
    s2 += __shfl_xor_sync(0xffffffffu, s2, 16);
    if (lane < 16) { redA[wid][lane] = s1; redB[wid][lane] = s2; }
    __syncthreads();
    if (tid < 16) {
        float S1 = 0.f, S2 = 0.f;
        #pragma unroll
        for (int w = 0; w < 8; w++) { S1 += redA[w][tid]; S2 += redB[w][tid]; }
        float mu  = S1 * (1.0f/CC);
        float var = S2 * (1.0f/CC) - mu*mu;
        muA[tid] = mu;
        rsA[tid] = rsqrtf(var + LN_EPS);
    }
    __syncthreads();
    float mu = muA[l], rs = rsA[l];
    float4 gv0 = *(const float4*)(g0 + c0),  gv1 = *(const float4*)(g0 + c0 + 4);
    float4 ev0 = *(const float4*)(be0 + c0), ev1 = *(const float4*)(be0 + c0 + 4);
    float* x2p = g_x2 + (n*LL + li)*CC + c0;
    float4 o0, o1;
    o0.x = (rv[0]-mu)*rs*gv0.x + ev0.x; o0.y = (rv[1]-mu)*rs*gv0.y + ev0.y;
    o0.z = (rv[2]-mu)*rs*gv0.z + ev0.z; o0.w = (rv[3]-mu)*rs*gv0.w + ev0.w;
    o1.x = (rv[4]-mu)*rs*gv1.x + ev1.x; o1.y = (rv[5]-mu)*rs*gv1.y + ev1.y;
    o1.z = (rv[6]-mu)*rs*gv1.z + ev1.z; o1.w = (rv[7]-mu)*rs*gv1.w + ev1.w;
    *(float4*)x2p = o0;
    *(float4*)(x2p + 4) = o1;
}

// ---------------- K3: fused FFN (unchanged from R3) ----------------
#define X2S_OFF 0
#define HT_OFF  4608            // X2S = 128 x 36
#define BS_OFF  23040           // HT  = 512 x 36
#define BS_STRIDE 8192          // BS  = 2 x 8192

__global__ __launch_bounds__(256) void k_ffn(
    const float* __restrict__ W0, const float* __restrict__ b0,
    const float* __restrict__ W1, const float* __restrict__ b1,
    const float* __restrict__ g1, const float* __restrict__ be1,
    float* __restrict__ out) {
    extern __shared__ float sm[];
    float* X2S = sm + X2S_OFF;
    float* HT  = sm + HT_OFF;
    float* BS  = sm + BS_OFF;

    int mb = blockIdx.x * 32;
    int n = mb >> 9, l0 = mb & 511;
    int tid = threadIdx.x;

    #pragma unroll
    for (int i = 0; i < 4; i++) {
        int idx = tid + i*256;
        int r = idx >> 5, c4 = (idx & 31) * 4;
        float4 v = *(const float4*)(g_x2 + (mb + r)*CC + c4);
        X2S[(c4+0)*36 + r] = v.x; X2S[(c4+1)*36 + r] = v.y;
        X2S[(c4+2)*36 + r] = v.z; X2S[(c4+3)*36 + r] = v.w;
    }

    int r0 = (tid & 3) * 8;
    int c0 = (tid >> 2) * 8;
    unsigned long long hacc[8][4];
    #pragma unroll
    for (int j = 0; j < 8; j++)
        #pragma unroll
        for (int rp = 0; rp < 4; rp++) hacc[j][rp] = 0ull;

    int buf = 0;
    #pragma unroll
    for (int i = 0; i < 8; i++) {
        int idx = tid + i*256;
        int k = idx >> 7, c4 = (idx & 127) * 4;
        cp16(&BS[k*512 + c4], W0 + k*FF + c4);
    }
    cp_commit();
    for (int kc = 0; kc < 8; kc++) {
        cp_wait0(); __syncthreads();
        if (kc < 7) {
            int kb = (kc+1)*16;
            float* dst = &BS[(buf^1)*BS_STRIDE];
            #pragma unroll
            for (int i = 0; i < 8; i++) {
                int idx = tid + i*256;
                int k = idx >> 7, c4 = (idx & 127) * 4;
                cp16(dst + k*512 + c4, W0 + (kb + k)*FF + c4);
            }
            cp_commit();
        }
        const float* bsb = &BS[buf*BS_STRIDE];
        #pragma unroll
        for (int k = 0; k < 16; k++) {
            int kg = kc*16 + k;
            ulonglong2 u0 = *(const ulonglong2*)&X2S[kg*36 + r0];
            ulonglong2 u1 = *(const ulonglong2*)&X2S[kg*36 + r0 + 4];
            float4 bA = *(const float4*)(bsb + k*512 + c0);
            float4 bB = *(const float4*)(bsb + k*512 + c0 + 4);
            float bv[8] = {bA.x,bA.y,bA.z,bA.w,bB.x,bB.y,bB.z,bB.w};
            #pragma unroll
            for (int j = 0; j < 8; j++) {
                unsigned long long bd = dup2(bv[j]);
                fma2(hacc[j][0], bd, u0.x);
                fma2(hacc[j][1], bd, u0.y);
                fma2(hacc[j][2], bd, u1.x);
                fma2(hacc[j][3], bd, u1.y);
            }
        }
        __syncthreads();
        buf ^= 1;
    }
    #pragma unroll
    for (int j = 0; j < 8; j++) {
        float bj = __ldg(b0 + c0 + j);
        float* dst = &HT[(c0+j)*36 + r0];
        #pragma unroll
        for (int rp = 0; rp < 4; rp++) {
            float p0, p1; unpack2(hacc[j][rp], p0, p1);
            dst[rp*2+0] = fmaxf(p0 + bj, 0.f);
            dst[rp*2+1] = fmaxf(p1 + bj, 0.f);
        }
    }
    __syncthreads();

    int r2 = (tid & 3) * 8;
    int c2 = (tid >> 2) * 2;
    unsigned long long xacc[2][4];
    #pragma unroll
    for (int j = 0; j < 2; j++)
        #pragma unroll
        for (int rp = 0; rp < 4; rp++) xacc[j][rp] = 0ull;

    buf = 0;
    #pragma unroll
    for (int i = 0; i < 4; i++) {
        int idx = tid + i*256;
        int k = idx >> 5, c4 = (idx & 31) * 4;
        cp16(&BS[k*128 + c4], W1 + k*CC + c4);
    }
    cp_commit();
    for (int kc = 0; kc < 16; kc++) {
        cp_wait0(); __syncthreads();
        if (kc < 15) {
            int kb = (kc+1)*32;
            float* dst = &BS[(buf^1)*BS_STRIDE];
            #pragma unroll
            for (int i = 0; i < 4; i++) {
                int idx = tid + i*256;
                int k = idx >> 5, c4 = (idx & 31) * 4;
                cp16(dst + k*128 + c4, W1 + (kb + k)*CC + c4);
            }
            cp_commit();
        }
        const float* bsb = &BS[buf*BS_STRIDE];
        #pragma unroll
        for (int k = 0; k < 32; k++) {
            int kg = kc*32 + k;
            ulonglong2 u0 = *(const ulonglong2*)&HT[kg*36 + r2];
            ulonglong2 u1 = *(const ulonglong2*)&HT[kg*36 + r2 + 4];
            float2 b2 = *(const float2*)(bsb + k*128 + c2);
            unsigned long long bd0 = dup2(b2.x);
            unsigned long long bd1 = dup2(b2.y);
            fma2(xacc[0][0], bd0, u0.x); fma2(xacc[0][1], bd0, u0.y);
            fma2(xacc[0][2], bd0, u1.x); fma2(xacc[0][3], bd0, u1.y);
            fma2(xacc[1][0], bd1, u0.x); fma2(xacc[1][1], bd1, u0.y);
            fma2(xacc[1][2], bd1, u1.x); fma2(xacc[1][3], bd1, u1.y);
        }
        __syncthreads();
        buf ^= 1;
    }

    float* YB = HT;
    #pragma unroll
    for (int j = 0; j < 2; j++) {
        float bj = __ldg(b1 + c2 + j);
        #pragma unroll
        for (int rp = 0; rp < 4; rp++) {
            float v0, v1; unpack2(xacc[j][rp], v0, v1);
            int ra = r2 + rp*2;
            v0 += bj + X2S[(c2+j)*36 + ra];
            v1 += bj + X2S[(c2+j)*36 + ra + 1];
            YB[(ra)*132 + c2 + j]   = v0;
            YB[(ra+1)*132 + c2 + j] = v1;
        }
    }
    __syncthreads();

    int wid = tid >> 5, lane = tid & 31;
    #pragma unroll
    for (int i = 0; i < 4; i++) {
        int row = wid*4 + i;
        float4 v = *(const float4*)&YB[row*132 + lane*4];
        float s1 = v.x + v.y + v.z + v.w;
        float s2 = v.x*v.x + v.y*v.y + v.z*v.z + v.w*v.w;
        #pragma unroll
        for (int o = 16; o > 0; o >>= 1) {
            s1 += __shfl_xor_sync(0xffffffffu, s1, o);
            s2 += __shfl_xor_sync(0xffffffffu, s2, o);
        }
        float mu  = s1 * (1.0f/CC);
        float var = s2 * (1.0f/CC) - mu*mu;
        float inv = rsqrtf(var + LN_EPS);
        float4 g = __ldg((const float4*)(g1 + lane*4));
        float4 e = __ldg((const float4*)(be1 + lane*4));
        v.x = (v.x - mu)*inv*g.x + e.x;
        v.y = (v.y - mu)*inv*g.y + e.y;
        v.z = (v.z - mu)*inv*g.z + e.z;
        v.w = (v.w - mu)*inv*g.w + e.w;
        *(float4*)&YB[row*132 + lane*4] = v;
    }
    __syncthreads();

    float* ob = out + n*CC*LL + l0;
    #pragma unroll
    for (int i = 0; i < 16; i++) {
        int idx = tid + i*256;
        int c = idx >> 5, l = idx & 31;
        ob[c*LL + l] = YB[l*132 + c];
    }
}

// ---------------- launch ----------------
extern "C" void kernel_launch(void* const* d_in, const int* in_sizes, int n_in,
                              void* d_out, int out_size) {
    const float* x   = (const float*)d_in[0];
    const float* Wx  = (const float*)d_in[1];
    const float* Wt  = (const float*)d_in[2];
    const float* bh  = (const float*)d_in[3];
    const float* Wa  = (const float*)d_in[4];
    // d_in[5] = ba: cancels in softmax; unused
    const float* W0  = (const float*)d_in[6];
    const float* b0  = (const float*)d_in[7];
    const float* W1  = (const float*)d_in[8];
    const float* b1  = (const float*)d_in[9];
    const float* g0  = (const float*)d_in[10];
    const float* be0 = (const float*)d_in[11];
    const float* g1  = (const float*)d_in[12];
    const float* be1 = (const float*)d_in[13];
    float* out  = (float*)d_out;
    float* aout = out + NN*CC*LL;  // second output: a (N,L,L)

    const int FFN_SMEM  = (23040 + 2*8192) * 4;   // 158,208 bytes
    const int PREP_SMEM = (128*36 + 128*128) * 4; // 83,968 bytes
    cudaFuncSetAttribute(k_ffn,  cudaFuncAttributeMaxDynamicSharedMemorySize, FFN_SMEM);
    cudaFuncSetAttribute(k_prep, cudaFuncAttributeMaxDynamicSharedMemorySize, PREP_SMEM);

    k_prep        <<<dim3(LL/32, NN), 256, PREP_SMEM>>>(x, Wt, Wx, bh);
    k_scores_fused<<<dim3(LL/16, NN), 256>>>(Wa, g0, be0, aout);
    k_ffn         <<<NN*LL/32, 256, FFN_SMEM>>>(W0, b0, W1, b1, g1, be1, out);
}

// round 5
// speedup vs baseline: 2.8003x; 1.0247x over previous
#include <cuda_runtime.h>

#define NN 8
#define CC 128
#define LL 512
#define DD 64
#define FF 512
#define LN_EPS 1e-5f
#define ATTN_EPS 1e-6f

// ---------------- scratch (static device globals; no allocation) ----------------
__device__ float g_xt[NN*LL*CC];   // (n,l,c)  2MB
__device__ float g_q [NN*LL*DD];   // q + bh   1MB
__device__ float g_k [NN*LL*DD];   // k        1MB
__device__ float g_x2[NN*LL*CC];   // post-LN0 2MB

__device__ __forceinline__ float tanh_fast(float x) {
    float e = __expf(-2.0f * fabsf(x));
    float t = __fdividef(1.0f - e, 1.0f + e);
    return copysignf(t, x);
}
__device__ __forceinline__ void fma2(unsigned long long& acc, unsigned long long a,
                                     unsigned long long b) {
    asm("fma.rn.f32x2 %0, %1, %2, %0;" : "+l"(acc) : "l"(a), "l"(b));
}
__device__ __forceinline__ unsigned long long dup2(float a) {
    unsigned long long r;
    asm("mov.b64 %0, {%1, %1};" : "=l"(r) : "f"(a));
    return r;
}
__device__ __forceinline__ void unpack2(unsigned long long v, float& lo, float& hi) {
    asm("mov.b64 {%0, %1}, %2;" : "=f"(lo), "=f"(hi) : "l"(v));
}
__device__ __forceinline__ void cp16(float* s, const float* g) {
    unsigned sa = (unsigned)__cvta_generic_to_shared(s);
    asm volatile("cp.async.cg.shared.global [%0], [%1], 16;" :: "r"(sa), "l"(g) : "memory");
}
__device__ __forceinline__ void cp_commit() {
    asm volatile("cp.async.commit_group;" ::: "memory");
}
__device__ __forceinline__ void cp_wait0() {
    asm volatile("cp.async.wait_group 0;" ::: "memory");
}

// ---------------- K1: split q/k GEMM: z=0 -> q = xt@Wt + bh (and xt transpose), z=1 -> k = xt@Wx ----------------
// grid (16, 8, 2), 256 thr, 50KB smem -> 2 blocks/SM, 16 warps/SM.
__global__ __launch_bounds__(256) void k_prep(
    const float* __restrict__ x, const float* __restrict__ Wt,
    const float* __restrict__ Wx, const float* __restrict__ bh) {
    extern __shared__ float sm[];
    float* XS = sm;            // [c=128][l=32 pad36]
    float* WS = sm + 128*36;   // [c=128][64]

    int n = blockIdx.y, l0 = blockIdx.x * 32;
    bool isq = (blockIdx.z == 0);
    const float* W = isq ? Wt : Wx;
    int tid = threadIdx.x;

    // stage weights via cp.async (overlaps with XS fill + transpose)
    #pragma unroll
    for (int i = 0; i < 8; i++) {
        int idx = tid + i*256;               // 2048 float4
        int row = idx >> 4, d4 = (idx & 15) * 4;
        cp16(&WS[row*64 + d4], W + row*DD + d4);
    }
    cp_commit();

    const float* xp = x + n*CC*LL + l0;
    #pragma unroll
    for (int i = 0; i < 16; i++) {
        int idx = tid + i*256;
        int c = idx >> 5, l = idx & 31;
        XS[c*36 + l] = xp[c*LL + l];
    }
    __syncthreads();

    if (isq) {
        float* xtp = g_xt + (n*LL + l0)*CC;
        #pragma unroll
        for (int i = 0; i < 16; i++) {
            int idx = tid + i*256;
            int l = idx >> 7, c = idx & 127;
            xtp[l*CC + c] = XS[c*36 + l];
        }
    }
    cp_wait0();
    __syncthreads();

    // GEMM 32 x 64 x 128; micro 4 rows x 2 cols; A broadcast, B contiguous float2
    int r0 = (tid >> 5) * 4;        // warp id -> row group (uniform in warp)
    int c0 = (tid & 31) * 2;        // lane -> col pair
    unsigned long long acc[2][2];
    acc[0][0] = acc[0][1] = acc[1][0] = acc[1][1] = 0ull;

    #pragma unroll 8
    for (int k = 0; k < CC; k++) {
        ulonglong2 a2 = *(const ulonglong2*)&XS[k*36 + r0];   // rows r0..r0+3 (broadcast)
        float2 b = *(const float2*)&WS[k*64 + c0];
        unsigned long long bd0 = dup2(b.x), bd1 = dup2(b.y);
        fma2(acc[0][0], bd0, a2.x); fma2(acc[0][1], bd0, a2.y);
        fma2(acc[1][0], bd1, a2.x); fma2(acc[1][1], bd1, a2.y);
    }

    float2 bhv = isq ? *(const float2*)(bh + c0) : make_float2(0.f, 0.f);
    float* base = isq ? g_q : g_k;
    int rowb = n*LL + l0 + r0;
    float c0lo, c0hi, c1lo, c1hi;
    unpack2(acc[0][0], c0lo, c0hi);
    unpack2(acc[1][0], c1lo, c1hi);
    *(float2*)(base + rowb*DD + c0)     = make_float2(c0lo + bhv.x, c1lo + bhv.y);
    *(float2*)(base + (rowb+1)*DD + c0) = make_float2(c0hi + bhv.x, c1hi + bhv.y);
    unpack2(acc[0][1], c0lo, c0hi);
    unpack2(acc[1][1], c1lo, c1hi);
    *(float2*)(base + (rowb+2)*DD + c0) = make_float2(c0lo + bhv.x, c1lo + bhv.y);
    *(float2*)(base + (rowb+3)*DD + c0) = make_float2(c0hi + bhv.x, c1hi + bhv.y);
}

// ---------------- K2: band scores + a write + attn-apply + LN0 (unchanged) ----------------
__global__ __launch_bounds__(256) void k_scores_fused(
    const float* __restrict__ Wa, const float* __restrict__ g0,
    const float* __restrict__ be0, float* __restrict__ aout) {
    __shared__ float  buf[79][132];
    __shared__ float  eb[16][65];
    __shared__ float4 was4[16];
    __shared__ float  redA[8][16];
    __shared__ float  redB[8][16];
    __shared__ float  rowmax[16], invs[16], muA[16], rsA[16];

    int n = blockIdx.y, l0 = blockIdx.x * 16;
    int tid = threadIdx.x;
    int l = tid & 15, mg = tid >> 4;
    int li = l0 + l;
    int wid = tid >> 5, lane = tid & 31;

    int mlo = l0 - 32; if (mlo < 0) mlo = 0;
    int mhi = l0 + 46; if (mhi > LL-1) mhi = LL-1;
    int nm  = mhi - mlo + 1;

    if (tid < 16) was4[tid] = *(const float4*)(Wa + tid*4);

    float4 rq[16];
    const float4* qrow = (const float4*)(g_q + (n*LL + li)*DD);
    #pragma unroll
    for (int dq = 0; dq < 16; dq++) rq[dq] = qrow[dq];

    const float* kbase = g_k + n*LL*DD;
    for (int idx4 = tid; idx4 < nm*16; idx4 += 256) {
        int r = idx4 >> 4, dq = idx4 & 15;
        *(float4*)&buf[r][dq*4] = __ldg((const float4*)(kbase + (mlo+r)*DD) + dq);
    }
    __syncthreads();

    float sv[4]; int vld[4];
    #pragma unroll
    for (int jj = 0; jj < 4; jj++) {
        int mo = mg*4 + jj;
        int m  = li - 32 + mo;
        vld[jj] = (m >= 0 && m < LL);
        float s = -1e30f;
        if (vld[jj]) {
            int r = m - mlo;
            s = 0.f;
            #pragma unroll 4
            for (int dq = 0; dq < 16; dq++) {
                float4 w  = was4[dq];
                float4 q  = rq[dq];
                float4 k4 = *(const float4*)&buf[r][dq*4];
                s += w.x * tanh_fast(q.x + k4.x);
                s += w.y * tanh_fast(q.y + k4.y);
                s += w.z * tanh_fast(q.z + k4.z);
                s += w.w * tanh_fast(q.w + k4.w);
            }
        }
        sv[jj] = s;
    }
    float rmax = fmaxf(fmaxf(sv[0], sv[1]), fmaxf(sv[2], sv[3]));
    rmax = fmaxf(rmax, __shfl_xor_sync(0xffffffffu, rmax, 16));
    if (lane < 16) redA[wid][lane] = rmax;
    __syncthreads();
    if (tid < 16) {
        float m = redA[0][tid];
        #pragma unroll
        for (int w = 1; w < 8; w++) m = fmaxf(m, redA[w][tid]);
        rowmax[tid] = m;
    }
    __syncthreads();
    float rm = rowmax[l];
    float esum = 0.f;
    #pragma unroll
    for (int jj = 0; jj < 4; jj++) {
        float e = vld[jj] ? __expf(sv[jj] - rm) : 0.f;
        eb[l][mg*4 + jj] = e;
        esum += e;
    }
    esum += __shfl_xor_sync(0xffffffffu, esum, 16);
    if (lane < 16) redA[wid][lane] = esum;
    __syncthreads();
    if (tid < 16) {
        float s = 0.f;
        #pragma unroll
        for (int w = 0; w < 8; w++) s += redA[w][tid];
        invs[tid] = __fdividef(1.0f, s + ATTN_EPS);
    }
    const float* xtn = g_xt + n*LL*CC;
    for (int idx4 = tid; idx4 < nm*32; idx4 += 256) {
        int r = idx4 >> 5, cq = idx4 & 31;
        *(float4*)&buf[r][cq*4] = *(const float4*)(xtn + (mlo+r)*CC + cq*4);
    }
    __syncthreads();

    float* ar = aout + (n*LL + l0)*LL;
    for (int idx = tid; idx < 16*LL; idx += 256) {
        int ll = idx >> 9, m = idx & 511;
        int mo = m - (l0 + ll - 32);
        float val = 0.f;
        if (mo >= 0 && mo < 64) val = eb[ll][mo] * invs[ll];
        ar[ll*LL + m] = val;
    }

    int c0 = mg * 8;
    int off = l0 + l - 32 - mlo;
    float acc[8];
    #pragma unroll
    for (int j = 0; j < 8; j++) acc[j] = 0.f;
    for (int mo = 0; mo < 64; mo++) {
        float w = eb[l][mo];
        int r = off + mo;
        r = min(max(r, 0), nm - 1);
        float4 xa = *(const float4*)&buf[r][c0];
        float4 xb = *(const float4*)&buf[r][c0+4];
        acc[0] += w*xa.x; acc[1] += w*xa.y; acc[2] += w*xa.z; acc[3] += w*xa.w;
        acc[4] += w*xb.x; acc[5] += w*xb.y; acc[6] += w*xb.z; acc[7] += w*xb.w;
    }
    float iv = invs[l];
    int rli = li - mlo;
    float4 ra = *(const float4*)&buf[rli][c0];
    float4 rb = *(const float4*)&buf[rli][c0+4];
    float rv[8];
    rv[0] = acc[0]*iv + ra.x; rv[1] = acc[1]*iv + ra.y;
    rv[2] = acc[2]*iv + ra.z; rv[3] = acc[3]*iv + ra.w;
    rv[4] = acc[4]*iv + rb.x; rv[5] = acc[5]*iv + rb.y;
    rv[6] = acc[6]*iv + rb.z; rv[7] = acc[7]*iv + rb.w;
    float s1 = 0.f, s2 = 0.f;
    #pragma unroll
    for (int j = 0; j < 8; j++) { s1 += rv[j]; s2 += rv[j]*rv[j]; }
    s1 += __shfl_xor_sync(0xffffffffu, s1, 16);
    s2 += __shfl_xor_sync(0xffffffffu, s2, 16);
    if (lane < 16) { redA[wid][lane] = s1; redB[wid][lane] = s2; }
    __syncthreads();
    if (tid < 16) {
        float S1 = 0.f, S2 = 0.f;
        #pragma unroll
        for (int w = 0; w < 8; w++) { S1 += redA[w][tid]; S2 += redB[w][tid]; }
        float mu  = S1 * (1.0f/CC);
        float var = S2 * (1.0f/CC) - mu*mu;
        muA[tid] = mu;
        rsA[tid] = rsqrtf(var + LN_EPS);
    }
    __syncthreads();
    float mu = muA[l], rs = rsA[l];
    float4 gv0 = *(const float4*)(g0 + c0),  gv1 = *(const float4*)(g0 + c0 + 4);
    float4 ev0 = *(const float4*)(be0 + c0), ev1 = *(const float4*)(be0 + c0 + 4);
    float* x2p = g_x2 + (n*LL + li)*CC + c0;
    float4 o0, o1;
    o0.x = (rv[0]-mu)*rs*gv0.x + ev0.x; o0.y = (rv[1]-mu)*rs*gv0.y + ev0.y;
    o0.z = (rv[2]-mu)*rs*gv0.z + ev0.z; o0.w = (rv[3]-mu)*rs*gv0.w + ev0.w;
    o1.x = (rv[4]-mu)*rs*gv1.x + ev1.x; o1.y = (rv[5]-mu)*rs*gv1.y + ev1.y;
    o1.z = (rv[6]-mu)*rs*gv1.z + ev1.z; o1.w = (rv[7]-mu)*rs*gv1.w + ev1.w;
    *(float4*)x2p = o0;
    *(float4*)(x2p + 4) = o1;
}

// ---------------- K3: fused FFN (unchanged) ----------------
#define X2S_OFF 0
#define HT_OFF  4608            // X2S = 128 x 36
#define BS_OFF  23040           // HT  = 512 x 36
#define BS_STRIDE 8192          // BS  = 2 x 8192

__global__ __launch_bounds__(256) void k_ffn(
    const float* __restrict__ W0, const float* __restrict__ b0,
    const float* __restrict__ W1, const float* __restrict__ b1,
    const float* __restrict__ g1, const float* __restrict__ be1,
    float* __restrict__ out) {
    extern __shared__ float sm[];
    float* X2S = sm + X2S_OFF;
    float* HT  = sm + HT_OFF;
    float* BS  = sm + BS_OFF;

    int mb = blockIdx.x * 32;
    int n = mb >> 9, l0 = mb & 511;
    int tid = threadIdx.x;

    #pragma unroll
    for (int i = 0; i < 4; i++) {
        int idx = tid + i*256;
        int r = idx >> 5, c4 = (idx & 31) * 4;
        float4 v = *(const float4*)(g_x2 + (mb + r)*CC + c4);
        X2S[(c4+0)*36 + r] = v.x; X2S[(c4+1)*36 + r] = v.y;
        X2S[(c4+2)*36 + r] = v.z; X2S[(c4+3)*36 + r] = v.w;
    }

    int r0 = (tid & 3) * 8;
    int c0 = (tid >> 2) * 8;
    unsigned long long hacc[8][4];
    #pragma unroll
    for (int j = 0; j < 8; j++)
        #pragma unroll
        for (int rp = 0; rp < 4; rp++) hacc[j][rp] = 0ull;

    int buf = 0;
    #pragma unroll
    for (int i = 0; i < 8; i++) {
        int idx = tid + i*256;
        int k = idx >> 7, c4 = (idx & 127) * 4;
        cp16(&BS[k*512 + c4], W0 + k*FF + c4);
    }
    cp_commit();
    for (int kc = 0; kc < 8; kc++) {
        cp_wait0(); __syncthreads();
        if (kc < 7) {
            int kb = (kc+1)*16;
            float* dst = &BS[(buf^1)*BS_STRIDE];
            #pragma unroll
            for (int i = 0; i < 8; i++) {
                int idx = tid + i*256;
                int k = idx >> 7, c4 = (idx & 127) * 4;
                cp16(dst + k*512 + c4, W0 + (kb + k)*FF + c4);
            }
            cp_commit();
        }
        const float* bsb = &BS[buf*BS_STRIDE];
        #pragma unroll
        for (int k = 0; k < 16; k++) {
            int kg = kc*16 + k;
            ulonglong2 u0 = *(const ulonglong2*)&X2S[kg*36 + r0];
            ulonglong2 u1 = *(const ulonglong2*)&X2S[kg*36 + r0 + 4];
            float4 bA = *(const float4*)(bsb + k*512 + c0);
            float4 bB = *(const float4*)(bsb + k*512 + c0 + 4);
            float bv[8] = {bA.x,bA.y,bA.z,bA.w,bB.x,bB.y,bB.z,bB.w};
            #pragma unroll
            for (int j = 0; j < 8; j++) {
                unsigned long long bd = dup2(bv[j]);
                fma2(hacc[j][0], bd, u0.x);
                fma2(hacc[j][1], bd, u0.y);
                fma2(hacc[j][2], bd, u1.x);
                fma2(hacc[j][3], bd, u1.y);
            }
        }
        __syncthreads();
        buf ^= 1;
    }
    #pragma unroll
    for (int j = 0; j < 8; j++) {
        float bj = __ldg(b0 + c0 + j);
        float* dst = &HT[(c0+j)*36 + r0];
        #pragma unroll
        for (int rp = 0; rp < 4; rp++) {
            float p0, p1; unpack2(hacc[j][rp], p0, p1);
            dst[rp*2+0] = fmaxf(p0 + bj, 0.f);
            dst[rp*2+1] = fmaxf(p1 + bj, 0.f);
        }
    }
    __syncthreads();

    int r2 = (tid & 3) * 8;
    int c2 = (tid >> 2) * 2;
    unsigned long long xacc[2][4];
    #pragma unroll
    for (int j = 0; j < 2; j++)
        #pragma unroll
        for (int rp = 0; rp < 4; rp++) xacc[j][rp] = 0ull;

    buf = 0;
    #pragma unroll
    for (int i = 0; i < 4; i++) {
        int idx = tid + i*256;
        int k = idx >> 5, c4 = (idx & 31) * 4;
        cp16(&BS[k*128 + c4], W1 + k*CC + c4);
    }
    cp_commit();
    for (int kc = 0; kc < 16; kc++) {
        cp_wait0(); __syncthreads();
        if (kc < 15) {
            int kb = (kc+1)*32;
            float* dst = &BS[(buf^1)*BS_STRIDE];
            #pragma unroll
            for (int i = 0; i < 4; i++) {
                int idx = tid + i*256;
                int k = idx >> 5, c4 = (idx & 31) * 4;
                cp16(dst + k*128 + c4, W1 + (kb + k)*CC + c4);
            }
            cp_commit();
        }
        const float* bsb = &BS[buf*BS_STRIDE];
        #pragma unroll
        for (int k = 0; k < 32; k++) {
            int kg = kc*32 + k;
            ulonglong2 u0 = *(const ulonglong2*)&HT[kg*36 + r2];
            ulonglong2 u1 = *(const ulonglong2*)&HT[kg*36 + r2 + 4];
            float2 b2 = *(const float2*)(bsb + k*128 + c2);
            unsigned long long bd0 = dup2(b2.x);
            unsigned long long bd1 = dup2(b2.y);
            fma2(xacc[0][0], bd0, u0.x); fma2(xacc[0][1], bd0, u0.y);
            fma2(xacc[0][2], bd0, u1.x); fma2(xacc[0][3], bd0, u1.y);
            fma2(xacc[1][0], bd1, u0.x); fma2(xacc[1][1], bd1, u0.y);
            fma2(xacc[1][2], bd1, u1.x); fma2(xacc[1][3], bd1, u1.y);
        }
        __syncthreads();
        buf ^= 1;
    }

    float* YB = HT;
    #pragma unroll
    for (int j = 0; j < 2; j++) {
        float bj = __ldg(b1 + c2 + j);
        #pragma unroll
        for (int rp = 0; rp < 4; rp++) {
            float v0, v1; unpack2(xacc[j][rp], v0, v1);
            int ra = r2 + rp*2;
            v0 += bj + X2S[(c2+j)*36 + ra];
            v1 += bj + X2S[(c2+j)*36 + ra + 1];
            YB[(ra)*132 + c2 + j]   = v0;
            YB[(ra+1)*132 + c2 + j] = v1;
        }
    }
    __syncthreads();

    int wid = tid >> 5, lane = tid & 31;
    #pragma unroll
    for (int i = 0; i < 4; i++) {
        int row = wid*4 + i;
        float4 v = *(const float4*)&YB[row*132 + lane*4];
        float s1 = v.x + v.y + v.z + v.w;
        float s2 = v.x*v.x + v.y*v.y + v.z*v.z + v.w*v.w;
        #pragma unroll
        for (int o = 16; o > 0; o >>= 1) {
            s1 += __shfl_xor_sync(0xffffffffu, s1, o);
            s2 += __shfl_xor_sync(0xffffffffu, s2, o);
        }
        float mu  = s1 * (1.0f/CC);
        float var = s2 * (1.0f/CC) - mu*mu;
        float inv = rsqrtf(var + LN_EPS);
        float4 g = __ldg((const float4*)(g1 + lane*4));
        float4 e = __ldg((const float4*)(be1 + lane*4));
        v.x = (v.x - mu)*inv*g.x + e.x;
        v.y = (v.y - mu)*inv*g.y + e.y;
        v.z = (v.z - mu)*inv*g.z + e.z;
        v.w = (v.w - mu)*inv*g.w + e.w;
        *(float4*)&YB[row*132 + lane*4] = v;
    }
    __syncthreads();

    float* ob = out + n*CC*LL + l0;
    #pragma unroll
    for (int i = 0; i < 16; i++) {
        int idx = tid + i*256;
        int c = idx >> 5, l = idx & 31;
        ob[c*LL + l] = YB[l*132 + c];
    }
}

// ---------------- launch ----------------
extern "C" void kernel_launch(void* const* d_in, const int* in_sizes, int n_in,
                              void* d_out, int out_size) {
    const float* x   = (const float*)d_in[0];
    const float* Wx  = (const float*)d_in[1];
    const float* Wt  = (const float*)d_in[2];
    const float* bh  = (const float*)d_in[3];
    const float* Wa  = (const float*)d_in[4];
    // d_in[5] = ba: cancels in softmax; unused
    const float* W0  = (const float*)d_in[6];
    const float* b0  = (const float*)d_in[7];
    const float* W1  = (const float*)d_in[8];
    const float* b1  = (const float*)d_in[9];
    const float* g0  = (const float*)d_in[10];
    const float* be0 = (const float*)d_in[11];
    const float* g1  = (const float*)d_in[12];
    const float* be1 = (const float*)d_in[13];
    float* out  = (float*)d_out;
    float* aout = out + NN*CC*LL;  // second output: a (N,L,L)

    const int FFN_SMEM  = (23040 + 2*8192) * 4;   // 158,208 bytes
    const int PREP_SMEM = (128*36 + 128*64) * 4;  // 51,200 bytes
    cudaFuncSetAttribute(k_ffn,  cudaFuncAttributeMaxDynamicSharedMemorySize, FFN_SMEM);
    cudaFuncSetAttribute(k_prep, cudaFuncAttributeMaxDynamicSharedMemorySize, PREP_SMEM);

    k_prep        <<<dim3(LL/32, NN, 2), 256, PREP_SMEM>>>(x, Wt, Wx, bh);
    k_scores_fused<<<dim3(LL/16, NN), 256>>>(Wa, g0, be0, aout);
    k_ffn         <<<NN*LL/32, 256, FFN_SMEM>>>(W0, b0, W1, b1, g1, be1, out);
}